// round 4
// baseline (speedup 1.0000x reference)
#include <cuda_runtime.h>
#include <math.h>

#define NPTS 65536
#define NS   16
#define CH   128
#define EPSB 1e-5f
#define LOG2E 1.4426950408889634f

typedef unsigned long long ull;

__device__ __forceinline__ ull pack2(float lo, float hi) {
    ull r; asm("mov.b64 %0,{%1,%2};" : "=l"(r) : "f"(lo), "f"(hi)); return r;
}
__device__ __forceinline__ void unpack2(ull v, float& lo, float& hi) {
    asm("mov.b64 {%0,%1},%2;" : "=f"(lo), "=f"(hi) : "l"(v));
}
__device__ __forceinline__ ull ffma2(ull a, ull b, ull c) {
    ull d; asm("fma.rn.f32x2 %0,%1,%2,%3;" : "=l"(d) : "l"(a), "l"(b), "l"(c)); return d;
}
__device__ __forceinline__ ull fmul2(ull a, ull b) {
    ull d; asm("mul.rn.f32x2 %0,%1,%2;" : "=l"(d) : "l"(a), "l"(b)); return d;
}
// volatile shared load: prevents ptxas from hoisting weights back into regs
__device__ __forceinline__ ull lds64v(unsigned addr) {
    ull v; asm volatile("ld.shared.b64 %0,[%1];" : "=l"(v) : "r"(addr)); return v;
}

// static device scratch (allocation-guard safe)
__device__ float  g_q[(size_t)NPTS * CH];
__device__ float  g_k[(size_t)NPTS * CH];
__device__ float  g_v[(size_t)NPTS * CH];
__device__ float4 g_p4[NPTS];

// ---------------------------------------------------------------------------
// prep: pack positions into float4
// ---------------------------------------------------------------------------
__global__ void prep_kernel(const float* __restrict__ p)
{
    int i = blockIdx.x * 256 + threadIdx.x;
    g_p4[i] = make_float4(p[3 * i + 0], p[3 * i + 1], p[3 * i + 2], 0.f);
}

// ---------------------------------------------------------------------------
// Kernel 1: QKV GEMM (round-2 proven version). 128x128 tile, 256 threads,
// 8x8 micro-tile, f32x2 FFMA2, K pipelined in 4 chunks of 32.
// grid = (512, 3): blockIdx.y selects q/k/v.
// ---------------------------------------------------------------------------
#define PADM 132

__global__ void __launch_bounds__(256)
qkv_kernel(const float* __restrict__ x,
           const float* __restrict__ wq, const float* __restrict__ bq,
           const float* __restrict__ wk, const float* __restrict__ bk,
           const float* __restrict__ wv, const float* __restrict__ bv)
{
    __shared__ float Xs[32][PADM];   // [k][m]
    __shared__ float Ws[32][PADM];   // [k][n]

    const int m0 = blockIdx.x * 128;
    const float* W;
    const float* bias;
    float* OUT;
    if (blockIdx.y == 0)      { W = wq; bias = bq; OUT = g_q; }
    else if (blockIdx.y == 1) { W = wk; bias = bk; OUT = g_k; }
    else                      { W = wv; bias = bv; OUT = g_v; }

    const int tid = threadIdx.x;
    const int tx  = tid & 15;    // n dir
    const int ty  = tid >> 4;    // m dir

    const int lrow = tid >> 3;          // 0..31
    const int kq   = (tid & 7) * 4;     // 0,4,..28

    ull acc2[8][4];
#pragma unroll
    for (int i = 0; i < 8; ++i)
#pragma unroll
        for (int j = 0; j < 4; ++j) acc2[i][j] = 0ull;

    float4 xpre[4], wpre[4];
#pragma unroll
    for (int l = 0; l < 4; ++l) {
        xpre[l] = *(const float4*)&x[(size_t)(m0 + lrow + 32 * l) * 128 + kq];
        wpre[l] = *(const float4*)&W[(size_t)(lrow + 32 * l) * 128 + kq];
    }

#pragma unroll
    for (int c = 0; c < 4; ++c) {
#pragma unroll
        for (int l = 0; l < 4; ++l) {
            int row = lrow + 32 * l;
            Xs[kq + 0][row] = xpre[l].x; Xs[kq + 1][row] = xpre[l].y;
            Xs[kq + 2][row] = xpre[l].z; Xs[kq + 3][row] = xpre[l].w;
            Ws[kq + 0][row] = wpre[l].x; Ws[kq + 1][row] = wpre[l].y;
            Ws[kq + 2][row] = wpre[l].z; Ws[kq + 3][row] = wpre[l].w;
        }
        __syncthreads();

        if (c < 3) {
            int kc = (c + 1) * 32;
#pragma unroll
            for (int l = 0; l < 4; ++l) {
                xpre[l] = *(const float4*)&x[(size_t)(m0 + lrow + 32 * l) * 128 + kc + kq];
                wpre[l] = *(const float4*)&W[(size_t)(lrow + 32 * l) * 128 + kc + kq];
            }
        }

#pragma unroll 8
        for (int k = 0; k < 32; ++k) {
            float4 a0 = *(const float4*)&Xs[k][ty * 8];
            float4 a1 = *(const float4*)&Xs[k][ty * 8 + 4];
            float4 b0 = *(const float4*)&Ws[k][tx * 8];
            float4 b1 = *(const float4*)&Ws[k][tx * 8 + 4];
            ull bb[4];
            bb[0] = pack2(b0.x, b0.y); bb[1] = pack2(b0.z, b0.w);
            bb[2] = pack2(b1.x, b1.y); bb[3] = pack2(b1.z, b1.w);
            float av[8] = {a0.x, a0.y, a0.z, a0.w, a1.x, a1.y, a1.z, a1.w};
#pragma unroll
            for (int i = 0; i < 8; ++i) {
                ull ai = pack2(av[i], av[i]);
#pragma unroll
                for (int j = 0; j < 4; ++j)
                    acc2[i][j] = ffma2(ai, bb[j], acc2[i][j]);
            }
        }
        __syncthreads();
    }

    float bs[8];
    {
        float4 t0 = *(const float4*)&bias[tx * 8];
        float4 t1 = *(const float4*)&bias[tx * 8 + 4];
        bs[0] = t0.x; bs[1] = t0.y; bs[2] = t0.z; bs[3] = t0.w;
        bs[4] = t1.x; bs[5] = t1.y; bs[6] = t1.z; bs[7] = t1.w;
    }
#pragma unroll
    for (int i = 0; i < 8; ++i) {
        float v[8];
#pragma unroll
        for (int j = 0; j < 4; ++j) unpack2(acc2[i][j], v[2 * j], v[2 * j + 1]);
        float4 o0 = make_float4(v[0] + bs[0], v[1] + bs[1], v[2] + bs[2], v[3] + bs[3]);
        float4 o1 = make_float4(v[4] + bs[4], v[5] + bs[5], v[6] + bs[6], v[7] + bs[7]);
        size_t base = (size_t)(m0 + ty * 8 + i) * 128 + tx * 8;
        *(float4*)&OUT[base]     = o0;
        *(float4*)&OUT[base + 4] = o1;
    }
}

// ---------------------------------------------------------------------------
// Kernel 2: per-point neighborhood attention.
// GEMV1 weights in SMEM (volatile LDS.64) -> regs <= 128 -> 16 warps/SM.
// ---------------------------------------------------------------------------
#define PPW 8

__global__ void __launch_bounds__(128, 4)
attn_kernel(const int* __restrict__ idx,
            const float* __restrict__ pw1, const float* __restrict__ pb1,
            const float* __restrict__ pbng, const float* __restrict__ pbnb,
            const float* __restrict__ pbnm, const float* __restrict__ pbnv,
            const float* __restrict__ pw2, const float* __restrict__ pb2,
            const float* __restrict__ bn1g, const float* __restrict__ bn1b,
            const float* __restrict__ bn1m, const float* __restrict__ bn1v,
            const float* __restrict__ ww1, const float* __restrict__ wb1,
            const float* __restrict__ bn2g, const float* __restrict__ bn2b,
            const float* __restrict__ bn2m, const float* __restrict__ bn2v,
            const float* __restrict__ ww2, const float* __restrict__ wb2,
            float* __restrict__ out)
{
    // ws1[j][r][lane] = pack2( ww1[(o^(2j))*CH + c_r], ww1[(o^(2j+1))*CH + c_r] )
    __shared__ ull ws1[8][4][32];

    const int tid  = threadIdx.x;
    const int lane = tid & 31;
    const int gw   = blockIdx.x * (blockDim.x >> 5) + (tid >> 5);
    const int o    = lane & 15;
    const int u0   = (lane & 16) ? 8 : 0;

    // cooperative build of the shared weight table (1024 entries, 128 thr)
#pragma unroll
    for (int e = tid; e < 1024; e += 128) {
        int j = e >> 7, r = (e >> 5) & 3, l = e & 31;
        int oo = l & 15, c = l + 32 * r;
        ws1[j][r][l] = pack2(ww1[(oo ^ (2 * j)) * CH + c],
                             ww1[(oo ^ (2 * j + 1)) * CH + c]);
    }
    __syncthreads();

    const unsigned wbase =
        (unsigned)__cvta_generic_to_shared(&ws1[0][0][0]) + lane * 8u;

    // GEMV2 half-row, log2e folded
    float w2r8[8];
#pragma unroll
    for (int u = 0; u < 8; ++u) w2r8[u] = ww2[o * 16 + u0 + u] * LOG2E;
    const float b2u = wb2[o] * LOG2E;

    const float s2    = bn2g[o] * rsqrtf(bn2v[o] + EPSB);
    const float b2fld = bn2b[o] - bn2m[o] * s2 + wb1[o] * s2;  // fold w1 bias

    float s1[4], b1f[4], pw2v[4][3], pb2v[4];
#pragma unroll
    for (int r = 0; r < 4; ++r) {
        int c = lane + 32 * r;
        float s = bn1g[c] * rsqrtf(bn1v[c] + EPSB);
        s1[r]  = s;
        b1f[r] = bn1b[c] - bn1m[c] * s;
        pw2v[r][0] = pw2[c * 3 + 0];
        pw2v[r][1] = pw2[c * 3 + 1];
        pw2v[r][2] = pw2[c * 3 + 2];
        pb2v[r] = pb2[c];
    }
    float Af[9], df[3];
#pragma unroll
    for (int a = 0; a < 3; ++a) {
        float s  = pbng[a] * rsqrtf(pbnv[a] + EPSB);
        float sh = pbnb[a] - pbnm[a] * s;
#pragma unroll
        for (int b = 0; b < 3; ++b) Af[a * 3 + b] = s * pw1[a * 3 + b];
        df[a] = s * pb1[a] + sh;
    }

#pragma unroll 1
    for (int t = 0; t < PPW; ++t) {
        const int i = gw * PPW + t;

        const float4 pi = g_p4[i];
        float xqf[4];
#pragma unroll
        for (int r = 0; r < 4; ++r) {
            float xq = g_q[(size_t)i * CH + lane + 32 * r];
            xqf[r] = b1f[r] - s1[r] * xq;
        }
        const int myj = idx[i * NS + o];

        float mrun = -INFINITY, Z = 0.f;
        float A[4] = {0.f, 0.f, 0.f, 0.f};

        int jA = __shfl_sync(0xffffffffu, myj, 0);
        float gkA[4], gvA[4];
#pragma unroll
        for (int r = 0; r < 4; ++r) {
            gkA[r] = g_k[(size_t)jA * CH + lane + 32 * r];
            gvA[r] = g_v[(size_t)jA * CH + lane + 32 * r];
        }
        float4 pjA = g_p4[jA];

#pragma unroll 2
        for (int n = 0; n < NS; ++n) {
            float gk[4], gv[4];
#pragma unroll
            for (int r = 0; r < 4; ++r) { gk[r] = gkA[r]; gv[r] = gvA[r]; }
            float pr0 = pjA.x - pi.x, pr1 = pjA.y - pi.y, pr2 = pjA.z - pi.z;

            if (n < NS - 1) {
                int jn = __shfl_sync(0xffffffffu, myj, n + 1);
#pragma unroll
                for (int r = 0; r < 4; ++r) {
                    gkA[r] = g_k[(size_t)jn * CH + lane + 32 * r];
                    gvA[r] = g_v[(size_t)jn * CH + lane + 32 * r];
                }
                pjA = g_p4[jn];
            }

            // linear_p stage 1 (BN folded)
            float tt[3];
#pragma unroll
            for (int a = 0; a < 3; ++a) {
                float v = fmaf(pr2, Af[a * 3 + 2],
                          fmaf(pr1, Af[a * 3 + 1],
                          fmaf(pr0, Af[a * 3 + 0], df[a])));
                tt[a] = fmaxf(v, 0.f);
            }
            // linear_p stage 2 + w-pre
            float pe[4], wp[4];
#pragma unroll
            for (int r = 0; r < 4; ++r) {
                pe[r] = fmaf(tt[2], pw2v[r][2],
                        fmaf(tt[1], pw2v[r][1],
                        fmaf(tt[0], pw2v[r][0], pb2v[r])));
                wp[r] = fmaxf(fmaf(gk[r] + pe[r], s1[r], xqf[r]), 0.f);
            }

            // GEMV1 partials: weights streamed from smem (volatile LDS.64)
            ull wp2[4];
#pragma unroll
            for (int r = 0; r < 4; ++r) wp2[r] = pack2(wp[r], wp[r]);
            float a[16];
#pragma unroll
            for (int j = 0; j < 8; ++j) {
                ull acc = fmul2(wp2[0], lds64v(wbase + j * 1024u));
                acc = ffma2(wp2[1], lds64v(wbase + j * 1024u + 256u), acc);
                acc = ffma2(wp2[2], lds64v(wbase + j * 1024u + 512u), acc);
                acc = ffma2(wp2[3], lds64v(wbase + j * 1024u + 768u), acc);
                unpack2(acc, a[2 * j], a[2 * j + 1]);
            }

            // XOR reduce-scatter
#pragma unroll
            for (int k = 0; k < 8; ++k) a[k] += __shfl_xor_sync(0xffffffffu, a[k + 8], 8);
#pragma unroll
            for (int k = 0; k < 4; ++k) a[k] += __shfl_xor_sync(0xffffffffu, a[k + 4], 4);
#pragma unroll
            for (int k = 0; k < 2; ++k) a[k] += __shfl_xor_sync(0xffffffffu, a[k + 2], 2);
            a[0] += __shfl_xor_sync(0xffffffffu, a[1], 1);
            float w1s = a[0] + __shfl_xor_sync(0xffffffffu, a[0], 16);

            // BN2 + ReLU
            float tv = fmaxf(fmaf(w1s, s2, b2fld), 0.f);

            // GEMV2 half-warp split
            float part = __shfl_sync(0xffffffffu, tv, u0) * w2r8[0];
#pragma unroll
            for (int u = 1; u < 8; ++u)
                part = fmaf(__shfl_sync(0xffffffffu, tv, u0 + u), w2r8[u], part);
            float w2v = part + __shfl_xor_sync(0xffffffffu, part, 16) + b2u;

            // online softmax, base 2
            float nm   = fmaxf(mrun, w2v);
            float corr = exp2f(mrun - nm);
            float e    = exp2f(w2v - nm);
            Z = fmaf(Z, corr, e);
#pragma unroll
            for (int r = 0; r < 4; ++r)
                A[r] = fmaf(A[r], corr, (gv[r] + pe[r]) * e);
            mrun = nm;
        }

        const float inv = __frcp_rn(Z);
#pragma unroll
        for (int r = 0; r < 4; ++r)
            out[(size_t)i * CH + lane + 32 * r] = A[r] * inv;
    }
}

// ---------------------------------------------------------------------------
extern "C" void kernel_launch(void* const* d_in, const int* in_sizes, int n_in,
                              void* d_out, int out_size)
{
    const float* p    = (const float*)d_in[0];
    const float* x    = (const float*)d_in[1];
    const int*   idx  = (const int*)  d_in[2];
    const float* wq   = (const float*)d_in[3];
    const float* bq   = (const float*)d_in[4];
    const float* wk   = (const float*)d_in[5];
    const float* bk   = (const float*)d_in[6];
    const float* wv   = (const float*)d_in[7];
    const float* bv   = (const float*)d_in[8];
    const float* pw1  = (const float*)d_in[9];
    const float* pb1  = (const float*)d_in[10];
    const float* pbng = (const float*)d_in[11];
    const float* pbnb = (const float*)d_in[12];
    const float* pbnm = (const float*)d_in[13];
    const float* pbnv = (const float*)d_in[14];
    const float* pw2  = (const float*)d_in[15];
    const float* pb2  = (const float*)d_in[16];
    const float* bn1g = (const float*)d_in[17];
    const float* bn1b = (const float*)d_in[18];
    const float* bn1m = (const float*)d_in[19];
    const float* bn1v = (const float*)d_in[20];
    const float* ww1  = (const float*)d_in[21];
    const float* wb1  = (const float*)d_in[22];
    const float* bn2g = (const float*)d_in[23];
    const float* bn2b = (const float*)d_in[24];
    const float* bn2m = (const float*)d_in[25];
    const float* bn2v = (const float*)d_in[26];
    const float* ww2  = (const float*)d_in[27];
    const float* wb2  = (const float*)d_in[28];
    float* out = (float*)d_out;

    prep_kernel<<<NPTS / 256, 256>>>(p);
    qkv_kernel<<<dim3(NPTS / 128, 3), 256>>>(x, wq, bq, wk, bk, wv, bv);

    attn_kernel<<<NPTS / (PPW * 4), 128>>>(
        idx,
        pw1, pb1, pbng, pbnb, pbnm, pbnv, pw2, pb2,
        bn1g, bn1b, bn1m, bn1v, ww1, wb1,
        bn2g, bn2b, bn2m, bn2v, ww2, wb2,
        out);
}

// round 5
// speedup vs baseline: 1.1529x; 1.1529x over previous
#include <cuda_runtime.h>
#include <math.h>

#define NPTS 65536
#define NS   16
#define CH   128
#define EPSB 1e-5f
#define LOG2E 1.4426950408889634f

typedef unsigned long long ull;

__device__ __forceinline__ ull pack2(float lo, float hi) {
    ull r; asm("mov.b64 %0,{%1,%2};" : "=l"(r) : "f"(lo), "f"(hi)); return r;
}
__device__ __forceinline__ void unpack2(ull v, float& lo, float& hi) {
    asm("mov.b64 {%0,%1},%2;" : "=f"(lo), "=f"(hi) : "l"(v));
}
__device__ __forceinline__ ull ffma2(ull a, ull b, ull c) {
    ull d; asm("fma.rn.f32x2 %0,%1,%2,%3;" : "=l"(d) : "l"(a), "l"(b), "l"(c)); return d;
}
__device__ __forceinline__ ull fmul2(ull a, ull b) {
    ull d; asm("mul.rn.f32x2 %0,%1,%2;" : "=l"(d) : "l"(a), "l"(b)); return d;
}

// static device scratch (allocation-guard safe)
__device__ float  g_q [(size_t)NPTS * CH];
__device__ float  g_k [(size_t)NPTS * CH];
__device__ float  g_v [(size_t)NPTS * CH];
__device__ float  g_kv[(size_t)NPTS * 2 * CH];   // float4-interleaved (k,v)
__device__ float4 g_p4[NPTS];

// ---------------------------------------------------------------------------
// prep: pack positions into float4
// ---------------------------------------------------------------------------
__global__ void prep_kernel(const float* __restrict__ p)
{
    int i = blockIdx.x * 256 + threadIdx.x;
    g_p4[i] = make_float4(p[3 * i + 0], p[3 * i + 1], p[3 * i + 2], 0.f);
}

// ---------------------------------------------------------------------------
// repack: g_k/g_v -> float4-interleaved g_kv.
// kv4[i*64 + l]      = {k[l],    k[l+32], v[l],    v[l+32]}
// kv4[i*64 + 32 + l] = {k[l+64], k[l+96], v[l+64], v[l+96]}
// ---------------------------------------------------------------------------
__global__ void repack_kernel()
{
    int t = blockIdx.x * 256 + threadIdx.x;
    int i = t >> 5, l = t & 31;
    const float* kb = &g_k[(size_t)i * CH];
    const float* vb = &g_v[(size_t)i * CH];
    float4* kv4 = (float4*)g_kv;
    kv4[(size_t)i * 64 + l]      = make_float4(kb[l],      kb[l + 32], vb[l],      vb[l + 32]);
    kv4[(size_t)i * 64 + 32 + l] = make_float4(kb[l + 64], kb[l + 96], vb[l + 64], vb[l + 96]);
}

// ---------------------------------------------------------------------------
// Kernel 1: QKV GEMM (round-2 proven, byte-identical). 128x128 tile,
// 256 threads, 8x8 micro-tile, f32x2 FFMA2, K in 4 chunks of 32.
// ---------------------------------------------------------------------------
#define PADM 132

__global__ void __launch_bounds__(256)
qkv_kernel(const float* __restrict__ x,
           const float* __restrict__ wq, const float* __restrict__ bq,
           const float* __restrict__ wk, const float* __restrict__ bk,
           const float* __restrict__ wv, const float* __restrict__ bv)
{
    __shared__ float Xs[32][PADM];   // [k][m]
    __shared__ float Ws[32][PADM];   // [k][n]

    const int m0 = blockIdx.x * 128;
    const float* W;
    const float* bias;
    float* OUT;
    if (blockIdx.y == 0)      { W = wq; bias = bq; OUT = g_q; }
    else if (blockIdx.y == 1) { W = wk; bias = bk; OUT = g_k; }
    else                      { W = wv; bias = bv; OUT = g_v; }

    const int tid = threadIdx.x;
    const int tx  = tid & 15;
    const int ty  = tid >> 4;

    const int lrow = tid >> 3;
    const int kq   = (tid & 7) * 4;

    ull acc2[8][4];
#pragma unroll
    for (int i = 0; i < 8; ++i)
#pragma unroll
        for (int j = 0; j < 4; ++j) acc2[i][j] = 0ull;

    float4 xpre[4], wpre[4];
#pragma unroll
    for (int l = 0; l < 4; ++l) {
        xpre[l] = *(const float4*)&x[(size_t)(m0 + lrow + 32 * l) * 128 + kq];
        wpre[l] = *(const float4*)&W[(size_t)(lrow + 32 * l) * 128 + kq];
    }

#pragma unroll
    for (int c = 0; c < 4; ++c) {
#pragma unroll
        for (int l = 0; l < 4; ++l) {
            int row = lrow + 32 * l;
            Xs[kq + 0][row] = xpre[l].x; Xs[kq + 1][row] = xpre[l].y;
            Xs[kq + 2][row] = xpre[l].z; Xs[kq + 3][row] = xpre[l].w;
            Ws[kq + 0][row] = wpre[l].x; Ws[kq + 1][row] = wpre[l].y;
            Ws[kq + 2][row] = wpre[l].z; Ws[kq + 3][row] = wpre[l].w;
        }
        __syncthreads();

        if (c < 3) {
            int kc = (c + 1) * 32;
#pragma unroll
            for (int l = 0; l < 4; ++l) {
                xpre[l] = *(const float4*)&x[(size_t)(m0 + lrow + 32 * l) * 128 + kc + kq];
                wpre[l] = *(const float4*)&W[(size_t)(lrow + 32 * l) * 128 + kc + kq];
            }
        }

#pragma unroll 8
        for (int k = 0; k < 32; ++k) {
            float4 a0 = *(const float4*)&Xs[k][ty * 8];
            float4 a1 = *(const float4*)&Xs[k][ty * 8 + 4];
            float4 b0 = *(const float4*)&Ws[k][tx * 8];
            float4 b1 = *(const float4*)&Ws[k][tx * 8 + 4];
            ull bb[4];
            bb[0] = pack2(b0.x, b0.y); bb[1] = pack2(b0.z, b0.w);
            bb[2] = pack2(b1.x, b1.y); bb[3] = pack2(b1.z, b1.w);
            float av[8] = {a0.x, a0.y, a0.z, a0.w, a1.x, a1.y, a1.z, a1.w};
#pragma unroll
            for (int i = 0; i < 8; ++i) {
                ull ai = pack2(av[i], av[i]);
#pragma unroll
                for (int j = 0; j < 4; ++j)
                    acc2[i][j] = ffma2(ai, bb[j], acc2[i][j]);
            }
        }
        __syncthreads();
    }

    float bs[8];
    {
        float4 t0 = *(const float4*)&bias[tx * 8];
        float4 t1 = *(const float4*)&bias[tx * 8 + 4];
        bs[0] = t0.x; bs[1] = t0.y; bs[2] = t0.z; bs[3] = t0.w;
        bs[4] = t1.x; bs[5] = t1.y; bs[6] = t1.z; bs[7] = t1.w;
    }
#pragma unroll
    for (int i = 0; i < 8; ++i) {
        float v[8];
#pragma unroll
        for (int j = 0; j < 4; ++j) unpack2(acc2[i][j], v[2 * j], v[2 * j + 1]);
        float4 o0 = make_float4(v[0] + bs[0], v[1] + bs[1], v[2] + bs[2], v[3] + bs[3]);
        float4 o1 = make_float4(v[4] + bs[4], v[5] + bs[5], v[6] + bs[6], v[7] + bs[7]);
        size_t base = (size_t)(m0 + ty * 8 + i) * 128 + tx * 8;
        *(float4*)&OUT[base]     = o0;
        *(float4*)&OUT[base + 4] = o1;
    }
}

// ---------------------------------------------------------------------------
// Kernel 2: per-point neighborhood attention (R2 skeleton + validated diets).
// Register weight cache for GEMV1; float4-interleaved kv gathers.
// ---------------------------------------------------------------------------
#define PPW 8

__global__ void __launch_bounds__(128, 3)
attn_kernel(const int* __restrict__ idx,
            const float* __restrict__ pw1, const float* __restrict__ pb1,
            const float* __restrict__ pbng, const float* __restrict__ pbnb,
            const float* __restrict__ pbnm, const float* __restrict__ pbnv,
            const float* __restrict__ pw2, const float* __restrict__ pb2,
            const float* __restrict__ bn1g, const float* __restrict__ bn1b,
            const float* __restrict__ bn1m, const float* __restrict__ bn1v,
            const float* __restrict__ ww1, const float* __restrict__ wb1,
            const float* __restrict__ bn2g, const float* __restrict__ bn2b,
            const float* __restrict__ bn2m, const float* __restrict__ bn2v,
            const float* __restrict__ ww2, const float* __restrict__ wb2,
            float* __restrict__ out)
{
    const int lane = threadIdx.x & 31;
    const int gw   = blockIdx.x * (blockDim.x >> 5) + (threadIdx.x >> 5);
    const int o    = lane & 15;
    const int u0   = (lane & 16) ? 8 : 0;

    // GEMV1 weights, XOR-permuted, f32x2-packed (64 regs)
    ull w1c2[8][4];
#pragma unroll
    for (int j = 0; j < 8; ++j)
#pragma unroll
        for (int r = 0; r < 4; ++r) {
            int c = lane + 32 * r;
            w1c2[j][r] = pack2(ww1[(o ^ (2 * j)) * CH + c],
                               ww1[(o ^ (2 * j + 1)) * CH + c]);
        }

    // GEMV2 half-row, log2e folded
    float w2r8[8];
#pragma unroll
    for (int u = 0; u < 8; ++u) w2r8[u] = ww2[o * 16 + u0 + u] * LOG2E;
    const float b2u = wb2[o] * LOG2E;

    const float s2    = bn2g[o] * rsqrtf(bn2v[o] + EPSB);
    const float b2fld = bn2b[o] - bn2m[o] * s2 + wb1[o] * s2;  // fold w1 bias

    float s1[4], b1f[4], pw2v[4][3], pb2v[4];
#pragma unroll
    for (int r = 0; r < 4; ++r) {
        int c = lane + 32 * r;
        float s = bn1g[c] * rsqrtf(bn1v[c] + EPSB);
        s1[r]  = s;
        b1f[r] = bn1b[c] - bn1m[c] * s;
        pw2v[r][0] = pw2[c * 3 + 0];
        pw2v[r][1] = pw2[c * 3 + 1];
        pw2v[r][2] = pw2[c * 3 + 2];
        pb2v[r] = pb2[c];
    }
    // linear_p stage 1 with BN folded
    float Af[9], df[3];
#pragma unroll
    for (int a = 0; a < 3; ++a) {
        float s  = pbng[a] * rsqrtf(pbnv[a] + EPSB);
        float sh = pbnb[a] - pbnm[a] * s;
#pragma unroll
        for (int b = 0; b < 3; ++b) Af[a * 3 + b] = s * pw1[a * 3 + b];
        df[a] = s * pb1[a] + sh;
    }

    const float4* kv4 = (const float4*)g_kv;

#pragma unroll 1
    for (int t = 0; t < PPW; ++t) {
        const int i = gw * PPW + t;

        const float4 pi = g_p4[i];
        float xqf[4];
#pragma unroll
        for (int r = 0; r < 4; ++r) {
            float xq = g_q[(size_t)i * CH + lane + 32 * r];
            xqf[r] = b1f[r] - s1[r] * xq;
        }
        const int myj = idx[i * NS + o];

        float mrun = -INFINITY, Z = 0.f;
        float A[4] = {0.f, 0.f, 0.f, 0.f};

        // prefetch neighbor 0
        int jA = __shfl_sync(0xffffffffu, myj, 0);
        float4 kvA0 = kv4[(size_t)jA * 64 + lane];
        float4 kvA1 = kv4[(size_t)jA * 64 + 32 + lane];
        float4 pjA  = g_p4[jA];

#pragma unroll 2
        for (int n = 0; n < NS; ++n) {
            float gk[4], gv[4];
            gk[0] = kvA0.x; gk[1] = kvA0.y; gk[2] = kvA1.x; gk[3] = kvA1.y;
            gv[0] = kvA0.z; gv[1] = kvA0.w; gv[2] = kvA1.z; gv[3] = kvA1.w;
            float pr0 = pjA.x - pi.x, pr1 = pjA.y - pi.y, pr2 = pjA.z - pi.z;

            if (n < NS - 1) {
                int jn = __shfl_sync(0xffffffffu, myj, n + 1);
                kvA0 = kv4[(size_t)jn * 64 + lane];
                kvA1 = kv4[(size_t)jn * 64 + 32 + lane];
                pjA  = g_p4[jn];
            }

            // linear_p stage 1 (BN folded)
            float tt[3];
#pragma unroll
            for (int a = 0; a < 3; ++a) {
                float v = fmaf(pr2, Af[a * 3 + 2],
                          fmaf(pr1, Af[a * 3 + 1],
                          fmaf(pr0, Af[a * 3 + 0], df[a])));
                tt[a] = fmaxf(v, 0.f);
            }
            // linear_p stage 2 + w-pre
            float pe[4], wp[4];
#pragma unroll
            for (int r = 0; r < 4; ++r) {
                pe[r] = fmaf(tt[2], pw2v[r][2],
                        fmaf(tt[1], pw2v[r][1],
                        fmaf(tt[0], pw2v[r][0], pb2v[r])));
                wp[r] = fmaxf(fmaf(gk[r] + pe[r], s1[r], xqf[r]), 0.f);
            }

            // GEMV1 partials (f32x2, XOR-permuted)
            ull wp2[4];
#pragma unroll
            for (int r = 0; r < 4; ++r) wp2[r] = pack2(wp[r], wp[r]);
            ull acc2[8];
#pragma unroll
            for (int j = 0; j < 8; ++j) {
                acc2[j] = fmul2(wp2[0], w1c2[j][0]);
                acc2[j] = ffma2(wp2[1], w1c2[j][1], acc2[j]);
                acc2[j] = ffma2(wp2[2], w1c2[j][2], acc2[j]);
                acc2[j] = ffma2(wp2[3], w1c2[j][3], acc2[j]);
            }
            float a[16];
#pragma unroll
            for (int j = 0; j < 8; ++j) unpack2(acc2[j], a[2 * j], a[2 * j + 1]);

            // XOR reduce-scatter
#pragma unroll
            for (int k = 0; k < 8; ++k) a[k] += __shfl_xor_sync(0xffffffffu, a[k + 8], 8);
#pragma unroll
            for (int k = 0; k < 4; ++k) a[k] += __shfl_xor_sync(0xffffffffu, a[k + 4], 4);
#pragma unroll
            for (int k = 0; k < 2; ++k) a[k] += __shfl_xor_sync(0xffffffffu, a[k + 2], 2);
            a[0] += __shfl_xor_sync(0xffffffffu, a[1], 1);
            float w1s = a[0] + __shfl_xor_sync(0xffffffffu, a[0], 16);

            // BN2 + ReLU
            float tv = fmaxf(fmaf(w1s, s2, b2fld), 0.f);

            // GEMV2 half-warp split
            float part = __shfl_sync(0xffffffffu, tv, u0) * w2r8[0];
#pragma unroll
            for (int u = 1; u < 8; ++u)
                part = fmaf(__shfl_sync(0xffffffffu, tv, u0 + u), w2r8[u], part);
            float w2v = part + __shfl_xor_sync(0xffffffffu, part, 16) + b2u;

            // online softmax, base 2
            float nm   = fmaxf(mrun, w2v);
            float corr = exp2f(mrun - nm);
            float e    = exp2f(w2v - nm);
            Z = fmaf(Z, corr, e);
#pragma unroll
            for (int r = 0; r < 4; ++r)
                A[r] = fmaf(A[r], corr, (gv[r] + pe[r]) * e);
            mrun = nm;
        }

        const float inv = __frcp_rn(Z);
#pragma unroll
        for (int r = 0; r < 4; ++r)
            out[(size_t)i * CH + lane + 32 * r] = A[r] * inv;
    }
}

// ---------------------------------------------------------------------------
extern "C" void kernel_launch(void* const* d_in, const int* in_sizes, int n_in,
                              void* d_out, int out_size)
{
    const float* p    = (const float*)d_in[0];
    const float* x    = (const float*)d_in[1];
    const int*   idx  = (const int*)  d_in[2];
    const float* wq   = (const float*)d_in[3];
    const float* bq   = (const float*)d_in[4];
    const float* wk   = (const float*)d_in[5];
    const float* bk   = (const float*)d_in[6];
    const float* wv   = (const float*)d_in[7];
    const float* bv   = (const float*)d_in[8];
    const float* pw1  = (const float*)d_in[9];
    const float* pb1  = (const float*)d_in[10];
    const float* pbng = (const float*)d_in[11];
    const float* pbnb = (const float*)d_in[12];
    const float* pbnm = (const float*)d_in[13];
    const float* pbnv = (const float*)d_in[14];
    const float* pw2  = (const float*)d_in[15];
    const float* pb2  = (const float*)d_in[16];
    const float* bn1g = (const float*)d_in[17];
    const float* bn1b = (const float*)d_in[18];
    const float* bn1m = (const float*)d_in[19];
    const float* bn1v = (const float*)d_in[20];
    const float* ww1  = (const float*)d_in[21];
    const float* wb1  = (const float*)d_in[22];
    const float* bn2g = (const float*)d_in[23];
    const float* bn2b = (const float*)d_in[24];
    const float* bn2m = (const float*)d_in[25];
    const float* bn2v = (const float*)d_in[26];
    const float* ww2  = (const float*)d_in[27];
    const float* wb2  = (const float*)d_in[28];
    float* out = (float*)d_out;

    prep_kernel<<<NPTS / 256, 256>>>(p);
    qkv_kernel<<<dim3(NPTS / 128, 3), 256>>>(x, wq, bq, wk, bk, wv, bv);
    repack_kernel<<<NPTS * 32 / 256, 256>>>();

    attn_kernel<<<NPTS / (PPW * 4), 128>>>(
        idx,
        pw1, pb1, pbng, pbnb, pbnm, pbnv, pw2, pb2,
        bn1g, bn1b, bn1m, bn1v, ww1, wb1,
        bn2g, bn2b, bn2m, bn2v, ww2, wb2,
        out);
}

// round 6
// speedup vs baseline: 1.1969x; 1.0381x over previous
#include <cuda_runtime.h>
#include <math.h>

#define NPTS 65536
#define NS   16
#define CH   128
#define EPSB 1e-5f
#define LOG2E 1.4426950408889634f

typedef unsigned long long ull;

__device__ __forceinline__ ull pack2(float lo, float hi) {
    ull r; asm("mov.b64 %0,{%1,%2};" : "=l"(r) : "f"(lo), "f"(hi)); return r;
}
__device__ __forceinline__ void unpack2(ull v, float& lo, float& hi) {
    asm("mov.b64 {%0,%1},%2;" : "=f"(lo), "=f"(hi) : "l"(v));
}
__device__ __forceinline__ ull ffma2(ull a, ull b, ull c) {
    ull d; asm("fma.rn.f32x2 %0,%1,%2,%3;" : "=l"(d) : "l"(a), "l"(b), "l"(c)); return d;
}
__device__ __forceinline__ ull fmul2(ull a, ull b) {
    ull d; asm("mul.rn.f32x2 %0,%1,%2;" : "=l"(d) : "l"(a), "l"(b)); return d;
}
__device__ __forceinline__ void cpasync16(unsigned dst, const void* src) {
    asm volatile("cp.async.ca.shared.global [%0],[%1],16;" :: "r"(dst), "l"(src));
}
__device__ __forceinline__ void cpcommit() {
    asm volatile("cp.async.commit_group;");
}
__device__ __forceinline__ void cpwait2() {
    asm volatile("cp.async.wait_group 2;");
}

// static device scratch (allocation-guard safe)
__device__ float  g_q [(size_t)NPTS * CH];
__device__ float  g_k [(size_t)NPTS * CH];
__device__ float  g_v [(size_t)NPTS * CH];
__device__ float  g_kv[(size_t)NPTS * 2 * CH];   // float4-interleaved (k,v)
__device__ float4 g_p4[NPTS];

// ---------------------------------------------------------------------------
__global__ void prep_kernel(const float* __restrict__ p)
{
    int i = blockIdx.x * 256 + threadIdx.x;
    g_p4[i] = make_float4(p[3 * i + 0], p[3 * i + 1], p[3 * i + 2], 0.f);
}

// kv4[i*64 + l]      = {k[l],    k[l+32], v[l],    v[l+32]}
// kv4[i*64 + 32 + l] = {k[l+64], k[l+96], v[l+64], v[l+96]}
__global__ void repack_kernel()
{
    int t = blockIdx.x * 256 + threadIdx.x;
    int i = t >> 5, l = t & 31;
    const float* kb = &g_k[(size_t)i * CH];
    const float* vb = &g_v[(size_t)i * CH];
    float4* kv4 = (float4*)g_kv;
    kv4[(size_t)i * 64 + l]      = make_float4(kb[l],      kb[l + 32], vb[l],      vb[l + 32]);
    kv4[(size_t)i * 64 + 32 + l] = make_float4(kb[l + 64], kb[l + 96], vb[l + 64], vb[l + 96]);
}

// ---------------------------------------------------------------------------
// Kernel 1: QKV GEMM (round-2 proven). 128x128 tile, 256 threads,
// 8x8 micro-tile, f32x2 FFMA2, K in 4 chunks of 32.
// ---------------------------------------------------------------------------
#define PADM 132

__global__ void __launch_bounds__(256)
qkv_kernel(const float* __restrict__ x,
           const float* __restrict__ wq, const float* __restrict__ bq,
           const float* __restrict__ wk, const float* __restrict__ bk,
           const float* __restrict__ wv, const float* __restrict__ bv)
{
    __shared__ float Xs[32][PADM];
    __shared__ float Ws[32][PADM];

    const int m0 = blockIdx.x * 128;
    const float* W;
    const float* bias;
    float* OUT;
    if (blockIdx.y == 0)      { W = wq; bias = bq; OUT = g_q; }
    else if (blockIdx.y == 1) { W = wk; bias = bk; OUT = g_k; }
    else                      { W = wv; bias = bv; OUT = g_v; }

    const int tid = threadIdx.x;
    const int tx  = tid & 15;
    const int ty  = tid >> 4;
    const int lrow = tid >> 3;
    const int kq   = (tid & 7) * 4;

    ull acc2[8][4];
#pragma unroll
    for (int i = 0; i < 8; ++i)
#pragma unroll
        for (int j = 0; j < 4; ++j) acc2[i][j] = 0ull;

    float4 xpre[4], wpre[4];
#pragma unroll
    for (int l = 0; l < 4; ++l) {
        xpre[l] = *(const float4*)&x[(size_t)(m0 + lrow + 32 * l) * 128 + kq];
        wpre[l] = *(const float4*)&W[(size_t)(lrow + 32 * l) * 128 + kq];
    }

#pragma unroll
    for (int c = 0; c < 4; ++c) {
#pragma unroll
        for (int l = 0; l < 4; ++l) {
            int row = lrow + 32 * l;
            Xs[kq + 0][row] = xpre[l].x; Xs[kq + 1][row] = xpre[l].y;
            Xs[kq + 2][row] = xpre[l].z; Xs[kq + 3][row] = xpre[l].w;
            Ws[kq + 0][row] = wpre[l].x; Ws[kq + 1][row] = wpre[l].y;
            Ws[kq + 2][row] = wpre[l].z; Ws[kq + 3][row] = wpre[l].w;
        }
        __syncthreads();

        if (c < 3) {
            int kc = (c + 1) * 32;
#pragma unroll
            for (int l = 0; l < 4; ++l) {
                xpre[l] = *(const float4*)&x[(size_t)(m0 + lrow + 32 * l) * 128 + kc + kq];
                wpre[l] = *(const float4*)&W[(size_t)(lrow + 32 * l) * 128 + kc + kq];
            }
        }

#pragma unroll 8
        for (int k = 0; k < 32; ++k) {
            float4 a0 = *(const float4*)&Xs[k][ty * 8];
            float4 a1 = *(const float4*)&Xs[k][ty * 8 + 4];
            float4 b0 = *(const float4*)&Ws[k][tx * 8];
            float4 b1 = *(const float4*)&Ws[k][tx * 8 + 4];
            ull bb[4];
            bb[0] = pack2(b0.x, b0.y); bb[1] = pack2(b0.z, b0.w);
            bb[2] = pack2(b1.x, b1.y); bb[3] = pack2(b1.z, b1.w);
            float av[8] = {a0.x, a0.y, a0.z, a0.w, a1.x, a1.y, a1.z, a1.w};
#pragma unroll
            for (int i = 0; i < 8; ++i) {
                ull ai = pack2(av[i], av[i]);
#pragma unroll
                for (int j = 0; j < 4; ++j)
                    acc2[i][j] = ffma2(ai, bb[j], acc2[i][j]);
            }
        }
        __syncthreads();
    }

    float bs[8];
    {
        float4 t0 = *(const float4*)&bias[tx * 8];
        float4 t1 = *(const float4*)&bias[tx * 8 + 4];
        bs[0] = t0.x; bs[1] = t0.y; bs[2] = t0.z; bs[3] = t0.w;
        bs[4] = t1.x; bs[5] = t1.y; bs[6] = t1.z; bs[7] = t1.w;
    }
#pragma unroll
    for (int i = 0; i < 8; ++i) {
        float v[8];
#pragma unroll
        for (int j = 0; j < 4; ++j) unpack2(acc2[i][j], v[2 * j], v[2 * j + 1]);
        float4 o0 = make_float4(v[0] + bs[0], v[1] + bs[1], v[2] + bs[2], v[3] + bs[3]);
        float4 o1 = make_float4(v[4] + bs[4], v[5] + bs[5], v[6] + bs[6], v[7] + bs[7]);
        size_t base = (size_t)(m0 + ty * 8 + i) * 128 + tx * 8;
        *(float4*)&OUT[base]     = o0;
        *(float4*)&OUT[base + 4] = o1;
    }
}

// ---------------------------------------------------------------------------
// Kernel 2: attention with cp.async depth-3 KV pipeline in smem.
// ---------------------------------------------------------------------------
#define PPW 8

__global__ void __launch_bounds__(128, 3)
attn_kernel(const int* __restrict__ idx,
            const float* __restrict__ pw1, const float* __restrict__ pb1,
            const float* __restrict__ pbng, const float* __restrict__ pbnb,
            const float* __restrict__ pbnm, const float* __restrict__ pbnv,
            const float* __restrict__ pw2, const float* __restrict__ pb2,
            const float* __restrict__ bn1g, const float* __restrict__ bn1b,
            const float* __restrict__ bn1m, const float* __restrict__ bn1v,
            const float* __restrict__ ww1, const float* __restrict__ wb1,
            const float* __restrict__ bn2g, const float* __restrict__ bn2b,
            const float* __restrict__ bn2m, const float* __restrict__ bn2v,
            const float* __restrict__ ww2, const float* __restrict__ wb2,
            float* __restrict__ out)
{
    // KV ring: [stage][warp][half][lane] float4; plus per-warp dummy slot
    __shared__ float4 ring[4][4][2][32];
    __shared__ float4 dummy[4][32];

    const int lane = threadIdx.x & 31;
    const int w    = (threadIdx.x >> 5) & 3;
    const int gw   = blockIdx.x * (blockDim.x >> 5) + (threadIdx.x >> 5);
    const int o    = lane & 15;
    const int u0   = (lane & 16) ? 8 : 0;

    const float4* kv4 = (const float4*)g_kv;

    // GEMV1 weights, XOR-permuted, f32x2-packed (64 regs)
    ull w1c2[8][4];
#pragma unroll
    for (int j = 0; j < 8; ++j)
#pragma unroll
        for (int r = 0; r < 4; ++r) {
            int c = lane + 32 * r;
            w1c2[j][r] = pack2(ww1[(o ^ (2 * j)) * CH + c],
                               ww1[(o ^ (2 * j + 1)) * CH + c]);
        }

    float w2r8[8];
#pragma unroll
    for (int u = 0; u < 8; ++u) w2r8[u] = ww2[o * 16 + u0 + u] * LOG2E;
    const float b2u = wb2[o] * LOG2E;

    const float s2    = bn2g[o] * rsqrtf(bn2v[o] + EPSB);
    const float b2fld = bn2b[o] - bn2m[o] * s2 + wb1[o] * s2;

    float s1[4], b1f[4], pw2v[4][3], pb2v[4];
#pragma unroll
    for (int r = 0; r < 4; ++r) {
        int c = lane + 32 * r;
        float s = bn1g[c] * rsqrtf(bn1v[c] + EPSB);
        s1[r]  = s;
        b1f[r] = bn1b[c] - bn1m[c] * s;
        pw2v[r][0] = pw2[c * 3 + 0];
        pw2v[r][1] = pw2[c * 3 + 1];
        pw2v[r][2] = pw2[c * 3 + 2];
        pb2v[r] = pb2[c];
    }
    float Af[9], df[3];
#pragma unroll
    for (int a = 0; a < 3; ++a) {
        float s  = pbng[a] * rsqrtf(pbnv[a] + EPSB);
        float sh = pbnb[a] - pbnm[a] * s;
#pragma unroll
        for (int b = 0; b < 3; ++b) Af[a * 3 + b] = s * pw1[a * 3 + b];
        df[a] = s * pb1[a] + sh;
    }

    const unsigned rb0 =
        (unsigned)__cvta_generic_to_shared(&ring[0][w][0][lane]);
    const unsigned db =
        (unsigned)__cvta_generic_to_shared(&dummy[w][lane]);

#pragma unroll 1
    for (int t = 0; t < PPW; ++t) {
        const int i = gw * PPW + t;

        const float4 pi = g_p4[i];
        float xqf[4];
#pragma unroll
        for (int r = 0; r < 4; ++r) {
            float xq = g_q[(size_t)i * CH + lane + 32 * r];
            xqf[r] = b1f[r] - s1[r] * xq;
        }
        const int myj = idx[i * NS + o];
        // all 16 neighbor positions: lane o holds p4[j_o]
        const float4 pjall = g_p4[myj];

        // prologue: issue KV stages 0..2
#pragma unroll
        for (int s = 0; s < 3; ++s) {
            int js = __shfl_sync(0xffffffffu, myj, s);
            cpasync16(rb0 + s * 4096u,        &kv4[(size_t)js * 64 + lane]);
            cpasync16(rb0 + s * 4096u + 512u, &kv4[(size_t)js * 64 + 32 + lane]);
            cpcommit();
        }

        float mrun = -INFINITY, Z = 0.f;
        float A[4] = {0.f, 0.f, 0.f, 0.f};

#pragma unroll 2
        for (int n = 0; n < NS; ++n) {
            cpwait2();
            const unsigned rs = rb0 + (unsigned)(n & 3) * 4096u;
            float4 kv0 = ring[n & 3][w][0][lane];
            float4 kv1 = ring[n & 3][w][1][lane];
            (void)rs;

            // keep 3 groups in flight (dummy near tail)
            if (n < NS - 3) {
                int jn = __shfl_sync(0xffffffffu, myj, n + 3);
                unsigned d = rb0 + (unsigned)((n + 3) & 3) * 4096u;
                cpasync16(d,        &kv4[(size_t)jn * 64 + lane]);
                cpasync16(d + 512u, &kv4[(size_t)jn * 64 + 32 + lane]);
            } else {
                cpasync16(db, &g_p4[0]);
            }
            cpcommit();

            float gk[4] = {kv0.x, kv0.y, kv1.x, kv1.y};
            float gv[4] = {kv0.z, kv0.w, kv1.z, kv1.w};
            float pr0 = __shfl_sync(0xffffffffu, pjall.x, n) - pi.x;
            float pr1 = __shfl_sync(0xffffffffu, pjall.y, n) - pi.y;
            float pr2 = __shfl_sync(0xffffffffu, pjall.z, n) - pi.z;

            // linear_p stage 1 (BN folded)
            float tt[3];
#pragma unroll
            for (int a = 0; a < 3; ++a) {
                float v = fmaf(pr2, Af[a * 3 + 2],
                          fmaf(pr1, Af[a * 3 + 1],
                          fmaf(pr0, Af[a * 3 + 0], df[a])));
                tt[a] = fmaxf(v, 0.f);
            }
            // linear_p stage 2 + w-pre
            float pe[4], wp[4];
#pragma unroll
            for (int r = 0; r < 4; ++r) {
                pe[r] = fmaf(tt[2], pw2v[r][2],
                        fmaf(tt[1], pw2v[r][1],
                        fmaf(tt[0], pw2v[r][0], pb2v[r])));
                wp[r] = fmaxf(fmaf(gk[r] + pe[r], s1[r], xqf[r]), 0.f);
            }

            // GEMV1 partials (f32x2, XOR-permuted)
            ull wp2[4];
#pragma unroll
            for (int r = 0; r < 4; ++r) wp2[r] = pack2(wp[r], wp[r]);
            ull acc2[8];
#pragma unroll
            for (int j = 0; j < 8; ++j) {
                acc2[j] = fmul2(wp2[0], w1c2[j][0]);
                acc2[j] = ffma2(wp2[1], w1c2[j][1], acc2[j]);
                acc2[j] = ffma2(wp2[2], w1c2[j][2], acc2[j]);
                acc2[j] = ffma2(wp2[3], w1c2[j][3], acc2[j]);
            }
            float a[16];
#pragma unroll
            for (int j = 0; j < 8; ++j) unpack2(acc2[j], a[2 * j], a[2 * j + 1]);

            // XOR reduce-scatter
#pragma unroll
            for (int k = 0; k < 8; ++k) a[k] += __shfl_xor_sync(0xffffffffu, a[k + 8], 8);
#pragma unroll
            for (int k = 0; k < 4; ++k) a[k] += __shfl_xor_sync(0xffffffffu, a[k + 4], 4);
#pragma unroll
            for (int k = 0; k < 2; ++k) a[k] += __shfl_xor_sync(0xffffffffu, a[k + 2], 2);
            a[0] += __shfl_xor_sync(0xffffffffu, a[1], 1);
            float w1s = a[0] + __shfl_xor_sync(0xffffffffu, a[0], 16);

            float tv = fmaxf(fmaf(w1s, s2, b2fld), 0.f);

            // GEMV2 half-warp split
            float part = __shfl_sync(0xffffffffu, tv, u0) * w2r8[0];
#pragma unroll
            for (int u = 1; u < 8; ++u)
                part = fmaf(__shfl_sync(0xffffffffu, tv, u0 + u), w2r8[u], part);
            float w2v = part + __shfl_xor_sync(0xffffffffu, part, 16) + b2u;

            // online softmax, base 2
            float nm   = fmaxf(mrun, w2v);
            float corr = exp2f(mrun - nm);
            float e    = exp2f(w2v - nm);
            Z = fmaf(Z, corr, e);
#pragma unroll
            for (int r = 0; r < 4; ++r)
                A[r] = fmaf(A[r], corr, (gv[r] + pe[r]) * e);
            mrun = nm;
        }

        const float inv = __frcp_rn(Z);
#pragma unroll
        for (int r = 0; r < 4; ++r)
            out[(size_t)i * CH + lane + 32 * r] = A[r] * inv;
    }
}

// ---------------------------------------------------------------------------
extern "C" void kernel_launch(void* const* d_in, const int* in_sizes, int n_in,
                              void* d_out, int out_size)
{
    const float* p    = (const float*)d_in[0];
    const float* x    = (const float*)d_in[1];
    const int*   idx  = (const int*)  d_in[2];
    const float* wq   = (const float*)d_in[3];
    const float* bq   = (const float*)d_in[4];
    const float* wk   = (const float*)d_in[5];
    const float* bk   = (const float*)d_in[6];
    const float* wv   = (const float*)d_in[7];
    const float* bv   = (const float*)d_in[8];
    const float* pw1  = (const float*)d_in[9];
    const float* pb1  = (const float*)d_in[10];
    const float* pbng = (const float*)d_in[11];
    const float* pbnb = (const float*)d_in[12];
    const float* pbnm = (const float*)d_in[13];
    const float* pbnv = (const float*)d_in[14];
    const float* pw2  = (const float*)d_in[15];
    const float* pb2  = (const float*)d_in[16];
    const float* bn1g = (const float*)d_in[17];
    const float* bn1b = (const float*)d_in[18];
    const float* bn1m = (const float*)d_in[19];
    const float* bn1v = (const float*)d_in[20];
    const float* ww1  = (const float*)d_in[21];
    const float* wb1  = (const float*)d_in[22];
    const float* bn2g = (const float*)d_in[23];
    const float* bn2b = (const float*)d_in[24];
    const float* bn2m = (const float*)d_in[25];
    const float* bn2v = (const float*)d_in[26];
    const float* ww2  = (const float*)d_in[27];
    const float* wb2  = (const float*)d_in[28];
    float* out = (float*)d_out;

    prep_kernel<<<NPTS / 256, 256>>>(p);
    qkv_kernel<<<dim3(NPTS / 128, 3), 256>>>(x, wq, bq, wk, bk, wv, bv);
    repack_kernel<<<NPTS * 32 / 256, 256>>>();

    attn_kernel<<<NPTS / (PPW * 4), 128>>>(
        idx,
        pw1, pb1, pbng, pbnb, pbnm, pbnv, pw2, pb2,
        bn1g, bn1b, bn1m, bn1v, ww1, wb1,
        bn2g, bn2b, bn2m, bn2v, ww2, wb2,
        out);
}

// round 7
// speedup vs baseline: 1.5310x; 1.2792x over previous
#include <cuda_runtime.h>
#include <math.h>

#define NPTS 65536
#define NS   16
#define CH   128
#define EPSB 1e-5f
#define LOG2E 1.4426950408889634f

typedef unsigned long long ull;

__device__ __forceinline__ ull pack2(float lo, float hi) {
    ull r; asm("mov.b64 %0,{%1,%2};" : "=l"(r) : "f"(lo), "f"(hi)); return r;
}
__device__ __forceinline__ void unpack2(ull v, float& lo, float& hi) {
    asm("mov.b64 {%0,%1},%2;" : "=f"(lo), "=f"(hi) : "l"(v));
}
__device__ __forceinline__ ull ffma2(ull a, ull b, ull c) {
    ull d; asm("fma.rn.f32x2 %0,%1,%2,%3;" : "=l"(d) : "l"(a), "l"(b), "l"(c)); return d;
}
__device__ __forceinline__ ull fmul2(ull a, ull b) {
    ull d; asm("mul.rn.f32x2 %0,%1,%2;" : "=l"(d) : "l"(a), "l"(b)); return d;
}
__device__ __forceinline__ void cpasync16(unsigned dst, const void* src) {
    asm volatile("cp.async.ca.shared.global [%0],[%1],16;" :: "r"(dst), "l"(src));
}
__device__ __forceinline__ void cpcommit() {
    asm volatile("cp.async.commit_group;");
}
__device__ __forceinline__ void cpwait2() {
    asm volatile("cp.async.wait_group 2;");
}
__device__ __forceinline__ unsigned f2tf32(float f) {
    unsigned u; asm("cvt.rna.tf32.f32 %0,%1;" : "=r"(u) : "f"(f)); return u;
}
__device__ __forceinline__ void mma_tf32(float c[4],
                                         unsigned a0, unsigned a1,
                                         unsigned a2, unsigned a3,
                                         unsigned b0, unsigned b1) {
    asm("mma.sync.aligned.m16n8k8.row.col.f32.tf32.tf32.f32 "
        "{%0,%1,%2,%3},{%4,%5,%6,%7},{%8,%9},{%0,%1,%2,%3};"
        : "+f"(c[0]), "+f"(c[1]), "+f"(c[2]), "+f"(c[3])
        : "r"(a0), "r"(a1), "r"(a2), "r"(a3), "r"(b0), "r"(b1));
}

// static device scratch (allocation-guard safe)
__device__ float  g_q [(size_t)NPTS * CH];
__device__ float  g_k [(size_t)NPTS * CH];
__device__ float  g_v [(size_t)NPTS * CH];
__device__ float  g_kv[(size_t)NPTS * 2 * CH];   // float4-interleaved (k,v)
__device__ float4 g_p4[NPTS];

// ---------------------------------------------------------------------------
__global__ void prep_kernel(const float* __restrict__ p)
{
    int i = blockIdx.x * 256 + threadIdx.x;
    g_p4[i] = make_float4(p[3 * i + 0], p[3 * i + 1], p[3 * i + 2], 0.f);
}

// kv4[i*64 + l]      = {k[l],    k[l+32], v[l],    v[l+32]}
// kv4[i*64 + 32 + l] = {k[l+64], k[l+96], v[l+64], v[l+96]}
__global__ void repack_kernel()
{
    int t = blockIdx.x * 256 + threadIdx.x;
    int i = t >> 5, l = t & 31;
    const float* kb = &g_k[(size_t)i * CH];
    const float* vb = &g_v[(size_t)i * CH];
    float4* kv4 = (float4*)g_kv;
    kv4[(size_t)i * 64 + l]      = make_float4(kb[l],      kb[l + 32], vb[l],      vb[l + 32]);
    kv4[(size_t)i * 64 + 32 + l] = make_float4(kb[l + 64], kb[l + 96], vb[l + 64], vb[l + 96]);
}

// ---------------------------------------------------------------------------
// Kernel 1: QKV GEMM on tensor cores (tf32 mma.sync.m16n8k8).
// Block 256 thr = 8 warps; tile 128(m)x128(n); warp -> 16x128 strip.
// K in 4 chunks of 32 staged in smem with tf32 conversion (pad 36: conflict-free).
// grid = (512, 3): blockIdx.y selects q/k/v.
// ---------------------------------------------------------------------------
__global__ void __launch_bounds__(256)
qkv_tc_kernel(const float* __restrict__ x,
              const float* __restrict__ wq, const float* __restrict__ bq,
              const float* __restrict__ wk, const float* __restrict__ bk,
              const float* __restrict__ wv, const float* __restrict__ bv)
{
    __shared__ unsigned Xs[128][36];
    __shared__ unsigned Ws[128][36];

    const float* W;
    const float* bias;
    float* OUT;
    if (blockIdx.y == 0)      { W = wq; bias = bq; OUT = g_q; }
    else if (blockIdx.y == 1) { W = wk; bias = bk; OUT = g_k; }
    else                      { W = wv; bias = bv; OUT = g_v; }

    const int tid  = threadIdx.x;
    const int warp = tid >> 5;
    const int lane = tid & 31;
    const int gid  = lane >> 2;   // 0..7
    const int tig  = lane & 3;    // 0..3
    const int m0   = blockIdx.x * 128;
    const int r0   = warp * 16;

    const int srow = tid >> 1;          // 0..127
    const int skq  = (tid & 1) * 16;    // 0 or 16

    float c[16][4];
#pragma unroll
    for (int nb = 0; nb < 16; ++nb)
#pragma unroll
        for (int j = 0; j < 4; ++j) c[nb][j] = 0.f;

#pragma unroll 1
    for (int ch = 0; ch < 4; ++ch) {
        // stage chunk (rows x 32 k-cols) with tf32 conversion
#pragma unroll
        for (int i = 0; i < 4; ++i) {
            float4 xv = *(const float4*)&x[(size_t)(m0 + srow) * 128 + ch * 32 + skq + 4 * i];
            float4 wv = *(const float4*)&W[(size_t)srow * 128 + ch * 32 + skq + 4 * i];
            uint4 xt, wt;
            xt.x = f2tf32(xv.x); xt.y = f2tf32(xv.y); xt.z = f2tf32(xv.z); xt.w = f2tf32(xv.w);
            wt.x = f2tf32(wv.x); wt.y = f2tf32(wv.y); wt.z = f2tf32(wv.z); wt.w = f2tf32(wv.w);
            *(uint4*)&Xs[srow][skq + 4 * i] = xt;
            *(uint4*)&Ws[srow][skq + 4 * i] = wt;
        }
        __syncthreads();

#pragma unroll
        for (int ks = 0; ks < 4; ++ks) {
            const int k = ks * 8;
            unsigned a0 = Xs[r0 + gid][k + tig];
            unsigned a1 = Xs[r0 + gid + 8][k + tig];
            unsigned a2 = Xs[r0 + gid][k + tig + 4];
            unsigned a3 = Xs[r0 + gid + 8][k + tig + 4];
#pragma unroll
            for (int nb = 0; nb < 16; ++nb) {
                unsigned b0 = Ws[nb * 8 + gid][k + tig];
                unsigned b1 = Ws[nb * 8 + gid][k + tig + 4];
                mma_tf32(c[nb], a0, a1, a2, a3, b0, b1);
            }
        }
        __syncthreads();
    }

    // epilogue: bias + store (c0,c1) / (c2,c3) as float2
#pragma unroll
    for (int nb = 0; nb < 16; ++nb) {
        const int col = nb * 8 + 2 * tig;
        const float2 bv = *(const float2*)&bias[col];
        const size_t row = (size_t)(m0 + r0 + gid);
        *(float2*)&OUT[row * 128 + col] =
            make_float2(c[nb][0] + bv.x, c[nb][1] + bv.y);
        *(float2*)&OUT[(row + 8) * 128 + col] =
            make_float2(c[nb][2] + bv.x, c[nb][3] + bv.y);
    }
}

// ---------------------------------------------------------------------------
// Kernel 2: attention (unchanged from round 6): cp.async depth-3 KV ring.
// ---------------------------------------------------------------------------
#define PPW 8

__global__ void __launch_bounds__(128, 3)
attn_kernel(const int* __restrict__ idx,
            const float* __restrict__ pw1, const float* __restrict__ pb1,
            const float* __restrict__ pbng, const float* __restrict__ pbnb,
            const float* __restrict__ pbnm, const float* __restrict__ pbnv,
            const float* __restrict__ pw2, const float* __restrict__ pb2,
            const float* __restrict__ bn1g, const float* __restrict__ bn1b,
            const float* __restrict__ bn1m, const float* __restrict__ bn1v,
            const float* __restrict__ ww1, const float* __restrict__ wb1,
            const float* __restrict__ bn2g, const float* __restrict__ bn2b,
            const float* __restrict__ bn2m, const float* __restrict__ bn2v,
            const float* __restrict__ ww2, const float* __restrict__ wb2,
            float* __restrict__ out)
{
    __shared__ float4 ring[4][4][2][32];
    __shared__ float4 dummy[4][32];

    const int lane = threadIdx.x & 31;
    const int w    = (threadIdx.x >> 5) & 3;
    const int gw   = blockIdx.x * (blockDim.x >> 5) + (threadIdx.x >> 5);
    const int o    = lane & 15;
    const int u0   = (lane & 16) ? 8 : 0;

    const float4* kv4 = (const float4*)g_kv;

    ull w1c2[8][4];
#pragma unroll
    for (int j = 0; j < 8; ++j)
#pragma unroll
        for (int r = 0; r < 4; ++r) {
            int c = lane + 32 * r;
            w1c2[j][r] = pack2(ww1[(o ^ (2 * j)) * CH + c],
                               ww1[(o ^ (2 * j + 1)) * CH + c]);
        }

    float w2r8[8];
#pragma unroll
    for (int u = 0; u < 8; ++u) w2r8[u] = ww2[o * 16 + u0 + u] * LOG2E;
    const float b2u = wb2[o] * LOG2E;

    const float s2    = bn2g[o] * rsqrtf(bn2v[o] + EPSB);
    const float b2fld = bn2b[o] - bn2m[o] * s2 + wb1[o] * s2;

    float s1[4], b1f[4], pw2v[4][3], pb2v[4];
#pragma unroll
    for (int r = 0; r < 4; ++r) {
        int c = lane + 32 * r;
        float s = bn1g[c] * rsqrtf(bn1v[c] + EPSB);
        s1[r]  = s;
        b1f[r] = bn1b[c] - bn1m[c] * s;
        pw2v[r][0] = pw2[c * 3 + 0];
        pw2v[r][1] = pw2[c * 3 + 1];
        pw2v[r][2] = pw2[c * 3 + 2];
        pb2v[r] = pb2[c];
    }
    float Af[9], df[3];
#pragma unroll
    for (int a = 0; a < 3; ++a) {
        float s  = pbng[a] * rsqrtf(pbnv[a] + EPSB);
        float sh = pbnb[a] - pbnm[a] * s;
#pragma unroll
        for (int b = 0; b < 3; ++b) Af[a * 3 + b] = s * pw1[a * 3 + b];
        df[a] = s * pb1[a] + sh;
    }

    const unsigned rb0 =
        (unsigned)__cvta_generic_to_shared(&ring[0][w][0][lane]);
    const unsigned db =
        (unsigned)__cvta_generic_to_shared(&dummy[w][lane]);

#pragma unroll 1
    for (int t = 0; t < PPW; ++t) {
        const int i = gw * PPW + t;

        const float4 pi = g_p4[i];
        float xqf[4];
#pragma unroll
        for (int r = 0; r < 4; ++r) {
            float xq = g_q[(size_t)i * CH + lane + 32 * r];
            xqf[r] = b1f[r] - s1[r] * xq;
        }
        const int myj = idx[i * NS + o];
        const float4 pjall = g_p4[myj];

#pragma unroll
        for (int s = 0; s < 3; ++s) {
            int js = __shfl_sync(0xffffffffu, myj, s);
            cpasync16(rb0 + s * 4096u,        &kv4[(size_t)js * 64 + lane]);
            cpasync16(rb0 + s * 4096u + 512u, &kv4[(size_t)js * 64 + 32 + lane]);
            cpcommit();
        }

        float mrun = -INFINITY, Z = 0.f;
        float A[4] = {0.f, 0.f, 0.f, 0.f};

#pragma unroll 2
        for (int n = 0; n < NS; ++n) {
            cpwait2();
            float4 kv0 = ring[n & 3][w][0][lane];
            float4 kv1 = ring[n & 3][w][1][lane];

            if (n < NS - 3) {
                int jn = __shfl_sync(0xffffffffu, myj, n + 3);
                unsigned d = rb0 + (unsigned)((n + 3) & 3) * 4096u;
                cpasync16(d,        &kv4[(size_t)jn * 64 + lane]);
                cpasync16(d + 512u, &kv4[(size_t)jn * 64 + 32 + lane]);
            } else {
                cpasync16(db, &g_p4[0]);
            }
            cpcommit();

            float gk[4] = {kv0.x, kv0.y, kv1.x, kv1.y};
            float gv[4] = {kv0.z, kv0.w, kv1.z, kv1.w};
            float pr0 = __shfl_sync(0xffffffffu, pjall.x, n) - pi.x;
            float pr1 = __shfl_sync(0xffffffffu, pjall.y, n) - pi.y;
            float pr2 = __shfl_sync(0xffffffffu, pjall.z, n) - pi.z;

            float tt[3];
#pragma unroll
            for (int a = 0; a < 3; ++a) {
                float v = fmaf(pr2, Af[a * 3 + 2],
                          fmaf(pr1, Af[a * 3 + 1],
                          fmaf(pr0, Af[a * 3 + 0], df[a])));
                tt[a] = fmaxf(v, 0.f);
            }
            float pe[4], wp[4];
#pragma unroll
            for (int r = 0; r < 4; ++r) {
                pe[r] = fmaf(tt[2], pw2v[r][2],
                        fmaf(tt[1], pw2v[r][1],
                        fmaf(tt[0], pw2v[r][0], pb2v[r])));
                wp[r] = fmaxf(fmaf(gk[r] + pe[r], s1[r], xqf[r]), 0.f);
            }

            ull wp2[4];
#pragma unroll
            for (int r = 0; r < 4; ++r) wp2[r] = pack2(wp[r], wp[r]);
            ull acc2[8];
#pragma unroll
            for (int j = 0; j < 8; ++j) {
                acc2[j] = fmul2(wp2[0], w1c2[j][0]);
                acc2[j] = ffma2(wp2[1], w1c2[j][1], acc2[j]);
                acc2[j] = ffma2(wp2[2], w1c2[j][2], acc2[j]);
                acc2[j] = ffma2(wp2[3], w1c2[j][3], acc2[j]);
            }
            float a[16];
#pragma unroll
            for (int j = 0; j < 8; ++j) unpack2(acc2[j], a[2 * j], a[2 * j + 1]);

#pragma unroll
            for (int k = 0; k < 8; ++k) a[k] += __shfl_xor_sync(0xffffffffu, a[k + 8], 8);
#pragma unroll
            for (int k = 0; k < 4; ++k) a[k] += __shfl_xor_sync(0xffffffffu, a[k + 4], 4);
#pragma unroll
            for (int k = 0; k < 2; ++k) a[k] += __shfl_xor_sync(0xffffffffu, a[k + 2], 2);
            a[0] += __shfl_xor_sync(0xffffffffu, a[1], 1);
            float w1s = a[0] + __shfl_xor_sync(0xffffffffu, a[0], 16);

            float tv = fmaxf(fmaf(w1s, s2, b2fld), 0.f);

            float part = __shfl_sync(0xffffffffu, tv, u0) * w2r8[0];
#pragma unroll
            for (int u = 1; u < 8; ++u)
                part = fmaf(__shfl_sync(0xffffffffu, tv, u0 + u), w2r8[u], part);
            float w2v = part + __shfl_xor_sync(0xffffffffu, part, 16) + b2u;

            float nm   = fmaxf(mrun, w2v);
            float corr = exp2f(mrun - nm);
            float e    = exp2f(w2v - nm);
            Z = fmaf(Z, corr, e);
#pragma unroll
            for (int r = 0; r < 4; ++r)
                A[r] = fmaf(A[r], corr, (gv[r] + pe[r]) * e);
            mrun = nm;
        }

        const float inv = __frcp_rn(Z);
#pragma unroll
        for (int r = 0; r < 4; ++r)
            out[(size_t)i * CH + lane + 32 * r] = A[r] * inv;
    }
}

// ---------------------------------------------------------------------------
extern "C" void kernel_launch(void* const* d_in, const int* in_sizes, int n_in,
                              void* d_out, int out_size)
{
    const float* p    = (const float*)d_in[0];
    const float* x    = (const float*)d_in[1];
    const int*   idx  = (const int*)  d_in[2];
    const float* wq   = (const float*)d_in[3];
    const float* bq   = (const float*)d_in[4];
    const float* wk   = (const float*)d_in[5];
    const float* bk   = (const float*)d_in[6];
    const float* wv   = (const float*)d_in[7];
    const float* bv   = (const float*)d_in[8];
    const float* pw1  = (const float*)d_in[9];
    const float* pb1  = (const float*)d_in[10];
    const float* pbng = (const float*)d_in[11];
    const float* pbnb = (const float*)d_in[12];
    const float* pbnm = (const float*)d_in[13];
    const float* pbnv = (const float*)d_in[14];
    const float* pw2  = (const float*)d_in[15];
    const float* pb2  = (const float*)d_in[16];
    const float* bn1g = (const float*)d_in[17];
    const float* bn1b = (const float*)d_in[18];
    const float* bn1m = (const float*)d_in[19];
    const float* bn1v = (const float*)d_in[20];
    const float* ww1  = (const float*)d_in[21];
    const float* wb1  = (const float*)d_in[22];
    const float* bn2g = (const float*)d_in[23];
    const float* bn2b = (const float*)d_in[24];
    const float* bn2m = (const float*)d_in[25];
    const float* bn2v = (const float*)d_in[26];
    const float* ww2  = (const float*)d_in[27];
    const float* wb2  = (const float*)d_in[28];
    float* out = (float*)d_out;

    prep_kernel<<<NPTS / 256, 256>>>(p);
    qkv_tc_kernel<<<dim3(NPTS / 128, 3), 256>>>(x, wq, bq, wk, bk, wv, bv);
    repack_kernel<<<NPTS * 32 / 256, 256>>>();

    attn_kernel<<<NPTS / (PPW * 4), 128>>>(
        idx,
        pw1, pb1, pbng, pbnb, pbnm, pbnv, pw2, pb2,
        bn1g, bn1b, bn1m, bn1v, ww1, wb1,
        bn2g, bn2b, bn2m, bn2v, ww2, wb2,
        out);
}

// round 8
// speedup vs baseline: 1.6528x; 1.0795x over previous
#include <cuda_runtime.h>
#include <math.h>

#define NPTS 65536
#define NS   16
#define CH   128
#define EPSB 1e-5f
#define LOG2E 1.4426950408889634f

typedef unsigned long long ull;

__device__ __forceinline__ ull pack2(float lo, float hi) {
    ull r; asm("mov.b64 %0,{%1,%2};" : "=l"(r) : "f"(lo), "f"(hi)); return r;
}
__device__ __forceinline__ void unpack2(ull v, float& lo, float& hi) {
    asm("mov.b64 {%0,%1},%2;" : "=f"(lo), "=f"(hi) : "l"(v));
}
__device__ __forceinline__ ull ffma2(ull a, ull b, ull c) {
    ull d; asm("fma.rn.f32x2 %0,%1,%2,%3;" : "=l"(d) : "l"(a), "l"(b), "l"(c)); return d;
}
__device__ __forceinline__ ull fmul2(ull a, ull b) {
    ull d; asm("mul.rn.f32x2 %0,%1,%2;" : "=l"(d) : "l"(a), "l"(b)); return d;
}
__device__ __forceinline__ void cpasync16(unsigned dst, const void* src) {
    asm volatile("cp.async.ca.shared.global [%0],[%1],16;" :: "r"(dst), "l"(src));
}
__device__ __forceinline__ void cpcommit() {
    asm volatile("cp.async.commit_group;");
}
__device__ __forceinline__ void cpwait1() {
    asm volatile("cp.async.wait_group 1;");
}
__device__ __forceinline__ unsigned f2tf32(float f) {
    unsigned u; asm("cvt.rna.tf32.f32 %0,%1;" : "=r"(u) : "f"(f)); return u;
}
__device__ __forceinline__ void mma_tf32(float c[4],
                                         unsigned a0, unsigned a1,
                                         unsigned a2, unsigned a3,
                                         unsigned b0, unsigned b1) {
    asm("mma.sync.aligned.m16n8k8.row.col.f32.tf32.tf32.f32 "
        "{%0,%1,%2,%3},{%4,%5,%6,%7},{%8,%9},{%0,%1,%2,%3};"
        : "+f"(c[0]), "+f"(c[1]), "+f"(c[2]), "+f"(c[3])
        : "r"(a0), "r"(a1), "r"(a2), "r"(a3), "r"(b0), "r"(b1));
}

// static device scratch (allocation-guard safe)
__device__ float  g_q [(size_t)NPTS * CH];
__device__ float  g_k [(size_t)NPTS * CH];
__device__ float  g_v [(size_t)NPTS * CH];
__device__ float  g_kv[(size_t)NPTS * 2 * CH];   // float4-interleaved (k,v)
__device__ float4 g_p4[NPTS];

// ---------------------------------------------------------------------------
__global__ void prep_kernel(const float* __restrict__ p)
{
    int i = blockIdx.x * 256 + threadIdx.x;
    g_p4[i] = make_float4(p[3 * i + 0], p[3 * i + 1], p[3 * i + 2], 0.f);
}

__global__ void repack_kernel()
{
    int t = blockIdx.x * 256 + threadIdx.x;
    int i = t >> 5, l = t & 31;
    const float* kb = &g_k[(size_t)i * CH];
    const float* vb = &g_v[(size_t)i * CH];
    float4* kv4 = (float4*)g_kv;
    kv4[(size_t)i * 64 + l]      = make_float4(kb[l],      kb[l + 32], vb[l],      vb[l + 32]);
    kv4[(size_t)i * 64 + 32 + l] = make_float4(kb[l + 64], kb[l + 96], vb[l + 64], vb[l + 96]);
}

// ---------------------------------------------------------------------------
// Kernel 1: QKV GEMM on tensor cores (tf32 mma.sync.m16n8k8) — R7 proven.
// ---------------------------------------------------------------------------
__global__ void __launch_bounds__(256)
qkv_tc_kernel(const float* __restrict__ x,
              const float* __restrict__ wq, const float* __restrict__ bq,
              const float* __restrict__ wk, const float* __restrict__ bk,
              const float* __restrict__ wv, const float* __restrict__ bv)
{
    __shared__ unsigned Xs[128][36];
    __shared__ unsigned Ws[128][36];

    const float* W;
    const float* bias;
    float* OUT;
    if (blockIdx.y == 0)      { W = wq; bias = bq; OUT = g_q; }
    else if (blockIdx.y == 1) { W = wk; bias = bk; OUT = g_k; }
    else                      { W = wv; bias = bv; OUT = g_v; }

    const int tid  = threadIdx.x;
    const int warp = tid >> 5;
    const int lane = tid & 31;
    const int gid  = lane >> 2;
    const int tig  = lane & 3;
    const int m0   = blockIdx.x * 128;
    const int r0   = warp * 16;

    const int srow = tid >> 1;
    const int skq  = (tid & 1) * 16;

    float c[16][4];
#pragma unroll
    for (int nb = 0; nb < 16; ++nb)
#pragma unroll
        for (int j = 0; j < 4; ++j) c[nb][j] = 0.f;

#pragma unroll 1
    for (int ch = 0; ch < 4; ++ch) {
#pragma unroll
        for (int i = 0; i < 4; ++i) {
            float4 xv = *(const float4*)&x[(size_t)(m0 + srow) * 128 + ch * 32 + skq + 4 * i];
            float4 wv = *(const float4*)&W[(size_t)srow * 128 + ch * 32 + skq + 4 * i];
            uint4 xt, wt;
            xt.x = f2tf32(xv.x); xt.y = f2tf32(xv.y); xt.z = f2tf32(xv.z); xt.w = f2tf32(xv.w);
            wt.x = f2tf32(wv.x); wt.y = f2tf32(wv.y); wt.z = f2tf32(wv.z); wt.w = f2tf32(wv.w);
            *(uint4*)&Xs[srow][skq + 4 * i] = xt;
            *(uint4*)&Ws[srow][skq + 4 * i] = wt;
        }
        __syncthreads();

#pragma unroll
        for (int ks = 0; ks < 4; ++ks) {
            const int k = ks * 8;
            unsigned a0 = Xs[r0 + gid][k + tig];
            unsigned a1 = Xs[r0 + gid + 8][k + tig];
            unsigned a2 = Xs[r0 + gid][k + tig + 4];
            unsigned a3 = Xs[r0 + gid + 8][k + tig + 4];
#pragma unroll
            for (int nb = 0; nb < 16; ++nb) {
                unsigned b0 = Ws[nb * 8 + gid][k + tig];
                unsigned b1 = Ws[nb * 8 + gid][k + tig + 4];
                mma_tf32(c[nb], a0, a1, a2, a3, b0, b1);
            }
        }
        __syncthreads();
    }

#pragma unroll
    for (int nb = 0; nb < 16; ++nb) {
        const int col = nb * 8 + 2 * tig;
        const float2 bv = *(const float2*)&bias[col];
        const size_t row = (size_t)(m0 + r0 + gid);
        *(float2*)&OUT[row * 128 + col] =
            make_float2(c[nb][0] + bv.x, c[nb][1] + bv.y);
        *(float2*)&OUT[(row + 8) * 128 + col] =
            make_float2(c[nb][2] + bv.x, c[nb][3] + bv.y);
    }
}

// ---------------------------------------------------------------------------
// Kernel 2: attention with two-neighbor interleaved bodies (even/odd softmax
// accumulators) + depth-8 cp.async KV ring (2 stages per group).
// ---------------------------------------------------------------------------
#define PPW 8

__global__ void __launch_bounds__(128, 3)
attn_kernel(const int* __restrict__ idx,
            const float* __restrict__ pw1, const float* __restrict__ pb1,
            const float* __restrict__ pbng, const float* __restrict__ pbnb,
            const float* __restrict__ pbnm, const float* __restrict__ pbnv,
            const float* __restrict__ pw2, const float* __restrict__ pb2,
            const float* __restrict__ bn1g, const float* __restrict__ bn1b,
            const float* __restrict__ bn1m, const float* __restrict__ bn1v,
            const float* __restrict__ ww1, const float* __restrict__ wb1,
            const float* __restrict__ bn2g, const float* __restrict__ bn2b,
            const float* __restrict__ bn2m, const float* __restrict__ bn2v,
            const float* __restrict__ ww2, const float* __restrict__ wb2,
            float* __restrict__ out)
{
    __shared__ float4 ring[8][4][2][32];   // [stage][warp][half][lane]
    __shared__ float4 dummy[4][32];

    const int lane = threadIdx.x & 31;
    const int w    = (threadIdx.x >> 5) & 3;
    const int gw   = blockIdx.x * (blockDim.x >> 5) + (threadIdx.x >> 5);
    const int o    = lane & 15;
    const int u0   = (lane & 16) ? 8 : 0;

    const float4* kv4 = (const float4*)g_kv;

    ull w1c2[8][4];
#pragma unroll
    for (int j = 0; j < 8; ++j)
#pragma unroll
        for (int r = 0; r < 4; ++r) {
            int c = lane + 32 * r;
            w1c2[j][r] = pack2(ww1[(o ^ (2 * j)) * CH + c],
                               ww1[(o ^ (2 * j + 1)) * CH + c]);
        }

    float w2r8[8];
#pragma unroll
    for (int u = 0; u < 8; ++u) w2r8[u] = ww2[o * 16 + u0 + u] * LOG2E;
    const float b2u = wb2[o] * LOG2E;

    const float s2    = bn2g[o] * rsqrtf(bn2v[o] + EPSB);
    const float b2fld = bn2b[o] - bn2m[o] * s2 + wb1[o] * s2;

    float s1[4], b1f[4], pw2v[4][3], pb2v[4];
#pragma unroll
    for (int r = 0; r < 4; ++r) {
        int c = lane + 32 * r;
        float s = bn1g[c] * rsqrtf(bn1v[c] + EPSB);
        s1[r]  = s;
        b1f[r] = bn1b[c] - bn1m[c] * s;
        pw2v[r][0] = pw2[c * 3 + 0];
        pw2v[r][1] = pw2[c * 3 + 1];
        pw2v[r][2] = pw2[c * 3 + 2];
        pb2v[r] = pb2[c];
    }
    float Af[9], df[3];
#pragma unroll
    for (int a = 0; a < 3; ++a) {
        float s  = pbng[a] * rsqrtf(pbnv[a] + EPSB);
        float sh = pbnb[a] - pbnm[a] * s;
#pragma unroll
        for (int b = 0; b < 3; ++b) Af[a * 3 + b] = s * pw1[a * 3 + b];
        df[a] = s * pb1[a] + sh;
    }

    const unsigned rb0 = (unsigned)__cvta_generic_to_shared(&ring[0][w][0][lane]);
    const unsigned db  = (unsigned)__cvta_generic_to_shared(&dummy[w][lane]);
    // stage s address offset: s * (4*2*32*16) = s*4096; half offset 512

#pragma unroll 1
    for (int t = 0; t < PPW; ++t) {
        const int i = gw * PPW + t;

        const float4 pi = g_p4[i];
        float xqf[4];
#pragma unroll
        for (int r = 0; r < 4; ++r) {
            float xq = g_q[(size_t)i * CH + lane + 32 * r];
            xqf[r] = b1f[r] - s1[r] * xq;
        }
        const int myj = idx[i * NS + o];
        const float4 pjall = g_p4[myj];

        // prologue: stages 0..3 in two groups of two
#pragma unroll
        for (int gpair = 0; gpair < 2; ++gpair) {
#pragma unroll
            for (int s = 2 * gpair; s < 2 * gpair + 2; ++s) {
                int js = __shfl_sync(0xffffffffu, myj, s);
                cpasync16(rb0 + s * 4096u,        &kv4[(size_t)js * 64 + lane]);
                cpasync16(rb0 + s * 4096u + 512u, &kv4[(size_t)js * 64 + 32 + lane]);
            }
            cpcommit();
        }

        float m0 = -INFINITY, m1 = -INFINITY, Z0 = 0.f, Z1 = 0.f;
        float A0[4] = {0.f, 0.f, 0.f, 0.f};
        float A1[4] = {0.f, 0.f, 0.f, 0.f};

#pragma unroll 2
        for (int h = 0; h < 8; ++h) {
            const int nA = 2 * h, nB = 2 * h + 1;
            cpwait1();
            const int sA = nA & 7, sB = nB & 7;
            float4 kvA0 = ring[sA][w][0][lane];
            float4 kvA1 = ring[sA][w][1][lane];
            float4 kvB0 = ring[sB][w][0][lane];
            float4 kvB1 = ring[sB][w][1][lane];

            // prefetch pair (nA+4, nB+4) or dummy near tail
            if (h < 6) {
                int j0 = __shfl_sync(0xffffffffu, myj, nA + 4);
                int j1 = __shfl_sync(0xffffffffu, myj, nB + 4);
                unsigned d0 = rb0 + (unsigned)((nA + 4) & 7) * 4096u;
                unsigned d1 = rb0 + (unsigned)((nB + 4) & 7) * 4096u;
                cpasync16(d0,        &kv4[(size_t)j0 * 64 + lane]);
                cpasync16(d0 + 512u, &kv4[(size_t)j0 * 64 + 32 + lane]);
                cpasync16(d1,        &kv4[(size_t)j1 * 64 + lane]);
                cpasync16(d1 + 512u, &kv4[(size_t)j1 * 64 + 32 + lane]);
            } else {
                cpasync16(db, &g_p4[0]);
            }
            cpcommit();

            // relative positions for both neighbors
            float prA0 = __shfl_sync(0xffffffffu, pjall.x, nA) - pi.x;
            float prA1 = __shfl_sync(0xffffffffu, pjall.y, nA) - pi.y;
            float prA2 = __shfl_sync(0xffffffffu, pjall.z, nA) - pi.z;
            float prB0 = __shfl_sync(0xffffffffu, pjall.x, nB) - pi.x;
            float prB1 = __shfl_sync(0xffffffffu, pjall.y, nB) - pi.y;
            float prB2 = __shfl_sync(0xffffffffu, pjall.z, nB) - pi.z;

            // linear_p stage 1 for both
            float ttA[3], ttB[3];
#pragma unroll
            for (int a = 0; a < 3; ++a) {
                float vA = fmaf(prA2, Af[a * 3 + 2],
                           fmaf(prA1, Af[a * 3 + 1],
                           fmaf(prA0, Af[a * 3 + 0], df[a])));
                float vB = fmaf(prB2, Af[a * 3 + 2],
                           fmaf(prB1, Af[a * 3 + 1],
                           fmaf(prB0, Af[a * 3 + 0], df[a])));
                ttA[a] = fmaxf(vA, 0.f);
                ttB[a] = fmaxf(vB, 0.f);
            }

            float gkA[4] = {kvA0.x, kvA0.y, kvA1.x, kvA1.y};
            float gvA[4] = {kvA0.z, kvA0.w, kvA1.z, kvA1.w};
            float gkB[4] = {kvB0.x, kvB0.y, kvB1.x, kvB1.y};
            float gvB[4] = {kvB0.z, kvB0.w, kvB1.z, kvB1.w};

            float peA[4], peB[4], wpA[4], wpB[4];
#pragma unroll
            for (int r = 0; r < 4; ++r) {
                peA[r] = fmaf(ttA[2], pw2v[r][2],
                         fmaf(ttA[1], pw2v[r][1],
                         fmaf(ttA[0], pw2v[r][0], pb2v[r])));
                peB[r] = fmaf(ttB[2], pw2v[r][2],
                         fmaf(ttB[1], pw2v[r][1],
                         fmaf(ttB[0], pw2v[r][0], pb2v[r])));
                wpA[r] = fmaxf(fmaf(gkA[r] + peA[r], s1[r], xqf[r]), 0.f);
                wpB[r] = fmaxf(fmaf(gkB[r] + peB[r], s1[r], xqf[r]), 0.f);
            }

            // GEMV1 partials for both (f32x2, XOR-permuted)
            ull wpA2[4], wpB2[4];
#pragma unroll
            for (int r = 0; r < 4; ++r) {
                wpA2[r] = pack2(wpA[r], wpA[r]);
                wpB2[r] = pack2(wpB[r], wpB[r]);
            }
            float aA[16], aB[16];
#pragma unroll
            for (int j = 0; j < 8; ++j) {
                ull accA = fmul2(wpA2[0], w1c2[j][0]);
                ull accB = fmul2(wpB2[0], w1c2[j][0]);
                accA = ffma2(wpA2[1], w1c2[j][1], accA);
                accB = ffma2(wpB2[1], w1c2[j][1], accB);
                accA = ffma2(wpA2[2], w1c2[j][2], accA);
                accB = ffma2(wpB2[2], w1c2[j][2], accB);
                accA = ffma2(wpA2[3], w1c2[j][3], accA);
                accB = ffma2(wpB2[3], w1c2[j][3], accB);
                unpack2(accA, aA[2 * j], aA[2 * j + 1]);
                unpack2(accB, aB[2 * j], aB[2 * j + 1]);
            }

            // interleaved XOR reduce-scatter (A and B chains overlap)
#pragma unroll
            for (int k = 0; k < 8; ++k) aA[k] += __shfl_xor_sync(0xffffffffu, aA[k + 8], 8);
#pragma unroll
            for (int k = 0; k < 8; ++k) aB[k] += __shfl_xor_sync(0xffffffffu, aB[k + 8], 8);
#pragma unroll
            for (int k = 0; k < 4; ++k) aA[k] += __shfl_xor_sync(0xffffffffu, aA[k + 4], 4);
#pragma unroll
            for (int k = 0; k < 4; ++k) aB[k] += __shfl_xor_sync(0xffffffffu, aB[k + 4], 4);
#pragma unroll
            for (int k = 0; k < 2; ++k) aA[k] += __shfl_xor_sync(0xffffffffu, aA[k + 2], 2);
#pragma unroll
            for (int k = 0; k < 2; ++k) aB[k] += __shfl_xor_sync(0xffffffffu, aB[k + 2], 2);
            aA[0] += __shfl_xor_sync(0xffffffffu, aA[1], 1);
            aB[0] += __shfl_xor_sync(0xffffffffu, aB[1], 1);
            float w1sA = aA[0] + __shfl_xor_sync(0xffffffffu, aA[0], 16);
            float w1sB = aB[0] + __shfl_xor_sync(0xffffffffu, aB[0], 16);

            float tvA = fmaxf(fmaf(w1sA, s2, b2fld), 0.f);
            float tvB = fmaxf(fmaf(w1sB, s2, b2fld), 0.f);

            // GEMV2 half-warp split for both
            float partA = __shfl_sync(0xffffffffu, tvA, u0) * w2r8[0];
            float partB = __shfl_sync(0xffffffffu, tvB, u0) * w2r8[0];
#pragma unroll
            for (int u = 1; u < 8; ++u) {
                partA = fmaf(__shfl_sync(0xffffffffu, tvA, u0 + u), w2r8[u], partA);
                partB = fmaf(__shfl_sync(0xffffffffu, tvB, u0 + u), w2r8[u], partB);
            }
            float w2vA = partA + __shfl_xor_sync(0xffffffffu, partA, 16) + b2u;
            float w2vB = partB + __shfl_xor_sync(0xffffffffu, partB, 16) + b2u;

            // two independent online-softmax accumulators (merged at end)
            {
                float nm = fmaxf(m0, w2vA);
                float corr = exp2f(m0 - nm);
                float e = exp2f(w2vA - nm);
                Z0 = fmaf(Z0, corr, e);
#pragma unroll
                for (int r = 0; r < 4; ++r)
                    A0[r] = fmaf(A0[r], corr, (gvA[r] + peA[r]) * e);
                m0 = nm;
            }
            {
                float nm = fmaxf(m1, w2vB);
                float corr = exp2f(m1 - nm);
                float e = exp2f(w2vB - nm);
                Z1 = fmaf(Z1, corr, e);
#pragma unroll
                for (int r = 0; r < 4; ++r)
                    A1[r] = fmaf(A1[r], corr, (gvB[r] + peB[r]) * e);
                m1 = nm;
            }
        }

        // merge even/odd accumulators
        const float mm = fmaxf(m0, m1);
        const float c0 = exp2f(m0 - mm);
        const float c1 = exp2f(m1 - mm);
        const float Z  = Z0 * c0 + Z1 * c1;
        const float inv = __frcp_rn(Z);
#pragma unroll
        for (int r = 0; r < 4; ++r)
            out[(size_t)i * CH + lane + 32 * r] =
                (A0[r] * c0 + A1[r] * c1) * inv;
    }
}

// ---------------------------------------------------------------------------
extern "C" void kernel_launch(void* const* d_in, const int* in_sizes, int n_in,
                              void* d_out, int out_size)
{
    const float* p    = (const float*)d_in[0];
    const float* x    = (const float*)d_in[1];
    const int*   idx  = (const int*)  d_in[2];
    const float* wq   = (const float*)d_in[3];
    const float* bq   = (const float*)d_in[4];
    const float* wk   = (const float*)d_in[5];
    const float* bk   = (const float*)d_in[6];
    const float* wv   = (const float*)d_in[7];
    const float* bv   = (const float*)d_in[8];
    const float* pw1  = (const float*)d_in[9];
    const float* pb1  = (const float*)d_in[10];
    const float* pbng = (const float*)d_in[11];
    const float* pbnb = (const float*)d_in[12];
    const float* pbnm = (const float*)d_in[13];
    const float* pbnv = (const float*)d_in[14];
    const float* pw2  = (const float*)d_in[15];
    const float* pb2  = (const float*)d_in[16];
    const float* bn1g = (const float*)d_in[17];
    const float* bn1b = (const float*)d_in[18];
    const float* bn1m = (const float*)d_in[19];
    const float* bn1v = (const float*)d_in[20];
    const float* ww1  = (const float*)d_in[21];
    const float* wb1  = (const float*)d_in[22];
    const float* bn2g = (const float*)d_in[23];
    const float* bn2b = (const float*)d_in[24];
    const float* bn2m = (const float*)d_in[25];
    const float* bn2v = (const float*)d_in[26];
    const float* ww2  = (const float*)d_in[27];
    const float* wb2  = (const float*)d_in[28];
    float* out = (float*)d_out;

    prep_kernel<<<NPTS / 256, 256>>>(p);
    qkv_tc_kernel<<<dim3(NPTS / 128, 3), 256>>>(x, wq, bq, wk, bk, wv, bv);
    repack_kernel<<<NPTS * 32 / 256, 256>>>();

    attn_kernel<<<NPTS / (PPW * 4), 128>>>(
        idx,
        pw1, pb1, pbng, pbnb, pbnm, pbnv, pw2, pb2,
        bn1g, bn1b, bn1m, bn1v, ww1, wb1,
        bn2g, bn2b, bn2m, bn2v, ww2, wb2,
        out);
}

// round 9
// speedup vs baseline: 1.9330x; 1.1695x over previous
#include <cuda_runtime.h>
#include <math.h>

#define NPTS 65536
#define NS   16
#define CH   128
#define EPSB 1e-5f
#define LOG2E 1.4426950408889634f

typedef unsigned long long ull;

__device__ __forceinline__ ull pack2(float lo, float hi) {
    ull r; asm("mov.b64 %0,{%1,%2};" : "=l"(r) : "f"(lo), "f"(hi)); return r;
}
__device__ __forceinline__ void unpack2(ull v, float& lo, float& hi) {
    asm("mov.b64 {%0,%1},%2;" : "=f"(lo), "=f"(hi) : "l"(v));
}
__device__ __forceinline__ ull ffma2(ull a, ull b, ull c) {
    ull d; asm("fma.rn.f32x2 %0,%1,%2,%3;" : "=l"(d) : "l"(a), "l"(b), "l"(c)); return d;
}
__device__ __forceinline__ void cpasync16(unsigned dst, const void* src) {
    asm volatile("cp.async.ca.shared.global [%0],[%1],16;" :: "r"(dst), "l"(src));
}
__device__ __forceinline__ void cpcommit() {
    asm volatile("cp.async.commit_group;");
}
__device__ __forceinline__ void cpwait2() {
    asm volatile("cp.async.wait_group 2;");
}
__device__ __forceinline__ unsigned f2tf32(float f) {
    unsigned u; asm("cvt.rna.tf32.f32 %0,%1;" : "=r"(u) : "f"(f)); return u;
}
__device__ __forceinline__ unsigned bf16x2hl(float hi, float lo) {
    unsigned d; asm("cvt.rn.bf16x2.f32 %0,%1,%2;" : "=r"(d) : "f"(hi), "f"(lo)); return d;
}
__device__ __forceinline__ void mma_tf32(float c[4],
                                         unsigned a0, unsigned a1,
                                         unsigned a2, unsigned a3,
                                         unsigned b0, unsigned b1) {
    asm("mma.sync.aligned.m16n8k8.row.col.f32.tf32.tf32.f32 "
        "{%0,%1,%2,%3},{%4,%5,%6,%7},{%8,%9},{%0,%1,%2,%3};"
        : "+f"(c[0]), "+f"(c[1]), "+f"(c[2]), "+f"(c[3])
        : "r"(a0), "r"(a1), "r"(a2), "r"(a3), "r"(b0), "r"(b1));
}
__device__ __forceinline__ void mma_bf16(float c[4],
                                         unsigned a0, unsigned a1,
                                         unsigned a2, unsigned a3,
                                         unsigned b0, unsigned b1) {
    asm("mma.sync.aligned.m16n8k16.row.col.f32.bf16.bf16.f32 "
        "{%0,%1,%2,%3},{%4,%5,%6,%7},{%8,%9},{%0,%1,%2,%3};"
        : "+f"(c[0]), "+f"(c[1]), "+f"(c[2]), "+f"(c[3])
        : "r"(a0), "r"(a1), "r"(a2), "r"(a3), "r"(b0), "r"(b1));
}

// static device scratch (allocation-guard safe)
__device__ float  g_q [(size_t)NPTS * CH];
__device__ float  g_k [(size_t)NPTS * CH];
__device__ float  g_v [(size_t)NPTS * CH];
__device__ float  g_kv[(size_t)NPTS * 2 * CH];
__device__ float4 g_p4[NPTS];

// ---------------------------------------------------------------------------
__global__ void prep_kernel(const float* __restrict__ p)
{
    int i = blockIdx.x * 256 + threadIdx.x;
    g_p4[i] = make_float4(p[3 * i + 0], p[3 * i + 1], p[3 * i + 2], 0.f);
}

__global__ void repack_kernel()
{
    int t = blockIdx.x * 256 + threadIdx.x;
    int i = t >> 5, l = t & 31;
    const float* kb = &g_k[(size_t)i * CH];
    const float* vb = &g_v[(size_t)i * CH];
    float4* kv4 = (float4*)g_kv;
    kv4[(size_t)i * 64 + l]      = make_float4(kb[l],      kb[l + 32], vb[l],      vb[l + 32]);
    kv4[(size_t)i * 64 + 32 + l] = make_float4(kb[l + 64], kb[l + 96], vb[l + 64], vb[l + 96]);
}

// ---------------------------------------------------------------------------
// Kernel 1: QKV GEMM on tensor cores (tf32 mma.m16n8k8) — proven (R7/R8).
// ---------------------------------------------------------------------------
__global__ void __launch_bounds__(256)
qkv_tc_kernel(const float* __restrict__ x,
              const float* __restrict__ wq, const float* __restrict__ bq,
              const float* __restrict__ wk, const float* __restrict__ bk,
              const float* __restrict__ wv, const float* __restrict__ bv)
{
    __shared__ unsigned Xs[128][36];
    __shared__ unsigned Ws[128][36];

    const float* W;
    const float* bias;
    float* OUT;
    if (blockIdx.y == 0)      { W = wq; bias = bq; OUT = g_q; }
    else if (blockIdx.y == 1) { W = wk; bias = bk; OUT = g_k; }
    else                      { W = wv; bias = bv; OUT = g_v; }

    const int tid  = threadIdx.x;
    const int warp = tid >> 5;
    const int lane = tid & 31;
    const int gid  = lane >> 2;
    const int tig  = lane & 3;
    const int m0   = blockIdx.x * 128;
    const int r0   = warp * 16;

    const int srow = tid >> 1;
    const int skq  = (tid & 1) * 16;

    float c[16][4];
#pragma unroll
    for (int nb = 0; nb < 16; ++nb)
#pragma unroll
        for (int j = 0; j < 4; ++j) c[nb][j] = 0.f;

#pragma unroll 1
    for (int ch = 0; ch < 4; ++ch) {
#pragma unroll
        for (int i = 0; i < 4; ++i) {
            float4 xv = *(const float4*)&x[(size_t)(m0 + srow) * 128 + ch * 32 + skq + 4 * i];
            float4 wv = *(const float4*)&W[(size_t)srow * 128 + ch * 32 + skq + 4 * i];
            uint4 xt, wt;
            xt.x = f2tf32(xv.x); xt.y = f2tf32(xv.y); xt.z = f2tf32(xv.z); xt.w = f2tf32(xv.w);
            wt.x = f2tf32(wv.x); wt.y = f2tf32(wv.y); wt.z = f2tf32(wv.z); wt.w = f2tf32(wv.w);
            *(uint4*)&Xs[srow][skq + 4 * i] = xt;
            *(uint4*)&Ws[srow][skq + 4 * i] = wt;
        }
        __syncthreads();

#pragma unroll
        for (int ks = 0; ks < 4; ++ks) {
            const int k = ks * 8;
            unsigned a0 = Xs[r0 + gid][k + tig];
            unsigned a1 = Xs[r0 + gid + 8][k + tig];
            unsigned a2 = Xs[r0 + gid][k + tig + 4];
            unsigned a3 = Xs[r0 + gid + 8][k + tig + 4];
#pragma unroll
            for (int nb = 0; nb < 16; ++nb) {
                unsigned b0 = Ws[nb * 8 + gid][k + tig];
                unsigned b1 = Ws[nb * 8 + gid][k + tig + 4];
                mma_tf32(c[nb], a0, a1, a2, a3, b0, b1);
            }
        }
        __syncthreads();
    }

#pragma unroll
    for (int nb = 0; nb < 16; ++nb) {
        const int col = nb * 8 + 2 * tig;
        const float2 bv = *(const float2*)&bias[col];
        const size_t row = (size_t)(m0 + r0 + gid);
        *(float2*)&OUT[row * 128 + col] =
            make_float2(c[nb][0] + bv.x, c[nb][1] + bv.y);
        *(float2*)&OUT[(row + 8) * 128 + col] =
            make_float2(c[nb][2] + bv.x, c[nb][3] + bv.y);
    }
}

// ---------------------------------------------------------------------------
// Kernel 2: tensor-core attention.
// Phase 1: stream 16 neighbors (cp.async ring), compute wp (bf16 -> smem) and
//          gv+pe (fp32 -> smem).
// Phase 2: mma.bf16 logits (16x16), BN2+ReLU, mma.tf32 GEMV2, fragment softmax,
//          smem transpose of weights, packed-f32x2 V accumulation.
// Dynamic smem 72KB/CTA -> 3 CTAs/SM.
// ---------------------------------------------------------------------------
#define PPW 8
#define SMEM_ATTN 73728
// offsets (bytes)
#define OFF_RING  0        // float4 [4 stages][4 warps][2 halves][32]  = 16384
#define OFF_DUMMY 16384    // float4 [4][32]                           =  2048
#define OFF_WSM   18432    // unsigned [4][16][68]                     = 17408
#define OFF_GSM   35840    // float2 [4][16][64]                       = 32768
#define OFF_WT    68608    // float [4][16][20]                        =  5120

__global__ void __launch_bounds__(128, 3)
attn_kernel(const int* __restrict__ idx,
            const float* __restrict__ pw1, const float* __restrict__ pb1,
            const float* __restrict__ pbng, const float* __restrict__ pbnb,
            const float* __restrict__ pbnm, const float* __restrict__ pbnv,
            const float* __restrict__ pw2, const float* __restrict__ pb2,
            const float* __restrict__ bn1g, const float* __restrict__ bn1b,
            const float* __restrict__ bn1m, const float* __restrict__ bn1v,
            const float* __restrict__ ww1, const float* __restrict__ wb1,
            const float* __restrict__ bn2g, const float* __restrict__ bn2b,
            const float* __restrict__ bn2m, const float* __restrict__ bn2v,
            const float* __restrict__ ww2, const float* __restrict__ wb2,
            float* __restrict__ out)
{
    extern __shared__ char dsm[];
    float4*   ringb = (float4*)(dsm + OFF_RING);
    float4*   dumb  = (float4*)(dsm + OFF_DUMMY);
    unsigned* wsm   = (unsigned*)(dsm + OFF_WSM);
    float2*   gsm   = (float2*)(dsm + OFF_GSM);
    float*    wtb   = (float*)(dsm + OFF_WT);

    const int lane = threadIdx.x & 31;
    const int w    = (threadIdx.x >> 5) & 3;
    const int gw   = blockIdx.x * (blockDim.x >> 5) + (threadIdx.x >> 5);
    const int gid  = lane >> 2;
    const int tig  = lane & 3;
    const int o    = lane & 15;

    const float4* kv4 = (const float4*)g_kv;

    // ---- W1 bf16 B-fragments: bw1[s][b][j], k-pair p = 8s+tig+4j,
    //      channels (c(p), c(p)+32) with c(p) = p<32 ? p : p+32, out col 8b+gid
    unsigned bw1[8][2][2];
#pragma unroll
    for (int s = 0; s < 8; ++s)
#pragma unroll
        for (int b = 0; b < 2; ++b)
#pragma unroll
            for (int j = 0; j < 2; ++j) {
                int p = 8 * s + tig + 4 * j;
                int c = (p < 32) ? p : p + 32;
                int oo = 8 * b + gid;
                bw1[s][b][j] = bf16x2hl(ww1[oo * CH + c + 32], ww1[oo * CH + c]);
            }

    // ---- W2 tf32 B-fragments (LOG2E folded): w2f[s][b][j], k=u=8s+tig+4j
    unsigned w2f[2][2][2];
#pragma unroll
    for (int s = 0; s < 2; ++s)
#pragma unroll
        for (int b = 0; b < 2; ++b)
#pragma unroll
            for (int j = 0; j < 2; ++j) {
                int u = 8 * s + tig + 4 * j;
                int oo = 8 * b + gid;
                w2f[s][b][j] = f2tf32(ww2[oo * 16 + u] * LOG2E);
            }

    // ---- BN2 constants for c-frag cols: class j = (e) + 2b -> u = 2tig+e+8b
    float s2c[4], b2c[4];
#pragma unroll
    for (int j = 0; j < 4; ++j) {
        int u = 2 * tig + (j & 1) + 8 * (j >> 1);
        float s = bn2g[u] * rsqrtf(bn2v[u] + EPSB);
        s2c[j] = s;
        b2c[j] = bn2b[u] - bn2m[u] * s + wb1[u] * s;   // fold w1 bias
    }

    float s1[4], b1f[4], pw2v[4][3], pb2v[4];
#pragma unroll
    for (int r = 0; r < 4; ++r) {
        int c = lane + 32 * r;
        float s = bn1g[c] * rsqrtf(bn1v[c] + EPSB);
        s1[r]  = s;
        b1f[r] = bn1b[c] - bn1m[c] * s;
        pw2v[r][0] = pw2[c * 3 + 0];
        pw2v[r][1] = pw2[c * 3 + 1];
        pw2v[r][2] = pw2[c * 3 + 2];
        pb2v[r] = pb2[c];
    }
    float Af[9], df[3];
#pragma unroll
    for (int a = 0; a < 3; ++a) {
        float s  = pbng[a] * rsqrtf(pbnv[a] + EPSB);
        float sh = pbnb[a] - pbnm[a] * s;
#pragma unroll
        for (int b = 0; b < 3; ++b) Af[a * 3 + b] = s * pw1[a * 3 + b];
        df[a] = s * pb1[a] + sh;
    }

    const unsigned rb0 =
        (unsigned)__cvta_generic_to_shared(&ringb[((0 * 4 + w) * 2 + 0) * 32 + lane]);
    const unsigned db =
        (unsigned)__cvta_generic_to_shared(&dumb[w * 32 + lane]);

#pragma unroll 1
    for (int t = 0; t < PPW; ++t) {
        const int i = gw * PPW + t;

        const float4 pi = g_p4[i];
        float xqf[4];
#pragma unroll
        for (int r = 0; r < 4; ++r) {
            float xq = g_q[(size_t)i * CH + lane + 32 * r];
            xqf[r] = b1f[r] - s1[r] * xq;
        }
        const int myj = idx[i * NS + o];
        const float4 pjall = g_p4[myj];

        // ---------------- Phase 1: stream neighbors ----------------
#pragma unroll
        for (int s = 0; s < 3; ++s) {
            int js = __shfl_sync(0xffffffffu, myj, s);
            cpasync16(rb0 + s * 4096u,        &kv4[(size_t)js * 64 + lane]);
            cpasync16(rb0 + s * 4096u + 512u, &kv4[(size_t)js * 64 + 32 + lane]);
            cpcommit();
        }

#pragma unroll
        for (int n = 0; n < NS; ++n) {
            cpwait2();
            float4 kv0 = ringb[(((n & 3) * 4 + w) * 2 + 0) * 32 + lane];
            float4 kv1 = ringb[(((n & 3) * 4 + w) * 2 + 1) * 32 + lane];

            if (n < NS - 3) {
                int jn = __shfl_sync(0xffffffffu, myj, n + 3);
                unsigned d = rb0 + (unsigned)((n + 3) & 3) * 4096u;
                cpasync16(d,        &kv4[(size_t)jn * 64 + lane]);
                cpasync16(d + 512u, &kv4[(size_t)jn * 64 + 32 + lane]);
            } else {
                cpasync16(db, &g_p4[0]);
            }
            cpcommit();

            float gk[4] = {kv0.x, kv0.y, kv1.x, kv1.y};
            float gv[4] = {kv0.z, kv0.w, kv1.z, kv1.w};
            float pr0 = __shfl_sync(0xffffffffu, pjall.x, n) - pi.x;
            float pr1 = __shfl_sync(0xffffffffu, pjall.y, n) - pi.y;
            float pr2 = __shfl_sync(0xffffffffu, pjall.z, n) - pi.z;

            float tt[3];
#pragma unroll
            for (int a = 0; a < 3; ++a) {
                float v = fmaf(pr2, Af[a * 3 + 2],
                          fmaf(pr1, Af[a * 3 + 1],
                          fmaf(pr0, Af[a * 3 + 0], df[a])));
                tt[a] = fmaxf(v, 0.f);
            }
            float pe[4], wp[4];
#pragma unroll
            for (int r = 0; r < 4; ++r) {
                pe[r] = fmaf(tt[2], pw2v[r][2],
                        fmaf(tt[1], pw2v[r][1],
                        fmaf(tt[0], pw2v[r][0], pb2v[r])));
                wp[r] = fmaxf(fmaf(gk[r] + pe[r], s1[r], xqf[r]), 0.f);
            }

            // store wp (bf16 pairs) and gv+pe (fp32 pairs)
            wsm[(w * 16 + n) * 68 + lane]      = bf16x2hl(wp[1], wp[0]);
            wsm[(w * 16 + n) * 68 + 32 + lane] = bf16x2hl(wp[3], wp[2]);
            gsm[(w * 16 + n) * 64 + lane]      = make_float2(gv[0] + pe[0], gv[1] + pe[1]);
            gsm[(w * 16 + n) * 64 + 32 + lane] = make_float2(gv[2] + pe[2], gv[3] + pe[3]);
        }
        __syncwarp();

        // ---------------- Phase 2: tensor-core logits ----------------
        float c1[2][4] = {{0.f, 0.f, 0.f, 0.f}, {0.f, 0.f, 0.f, 0.f}};
#pragma unroll
        for (int s = 0; s < 8; ++s) {
            unsigned a0 = wsm[(w * 16 + gid)     * 68 + 8 * s + tig];
            unsigned a1 = wsm[(w * 16 + gid + 8) * 68 + 8 * s + tig];
            unsigned a2 = wsm[(w * 16 + gid)     * 68 + 8 * s + tig + 4];
            unsigned a3 = wsm[(w * 16 + gid + 8) * 68 + 8 * s + tig + 4];
            mma_bf16(c1[0], a0, a1, a2, a3, bw1[s][0][0], bw1[s][0][1]);
            mma_bf16(c1[1], a0, a1, a2, a3, bw1[s][1][0], bw1[s][1][1]);
        }

        // BN2 + ReLU on c-fragments
        float t1[2][4];
#pragma unroll
        for (int b = 0; b < 2; ++b)
#pragma unroll
            for (int q = 0; q < 4; ++q)
                t1[b][q] = fmaxf(fmaf(c1[b][q], s2c[(q & 1) + 2 * b],
                                      b2c[(q & 1) + 2 * b]), 0.f);

        // permute t (c-frag) -> A-frags for GEMV2
        const int srcA = 4 * gid + (tig >> 1);
        const bool oddt = (tig & 1);
        unsigned aa[2][4];
#pragma unroll
        for (int s = 0; s < 2; ++s) {
            float v0 = __shfl_sync(0xffffffffu, t1[s][0], srcA);
            float v1 = __shfl_sync(0xffffffffu, t1[s][1], srcA);
            float v2 = __shfl_sync(0xffffffffu, t1[s][2], srcA);
            float v3 = __shfl_sync(0xffffffffu, t1[s][3], srcA);
            float u0v = oddt ? v1 : v0;
            float u1v = oddt ? v3 : v2;
            float q0 = __shfl_sync(0xffffffffu, t1[s][0], srcA + 2);
            float q1 = __shfl_sync(0xffffffffu, t1[s][1], srcA + 2);
            float q2 = __shfl_sync(0xffffffffu, t1[s][2], srcA + 2);
            float q3 = __shfl_sync(0xffffffffu, t1[s][3], srcA + 2);
            float u2v = oddt ? q1 : q0;
            float u3v = oddt ? q3 : q2;
            aa[s][0] = f2tf32(u0v); aa[s][1] = f2tf32(u1v);
            aa[s][2] = f2tf32(u2v); aa[s][3] = f2tf32(u3v);
        }

        float c2[2][4] = {{0.f, 0.f, 0.f, 0.f}, {0.f, 0.f, 0.f, 0.f}};
#pragma unroll
        for (int s = 0; s < 2; ++s) {
            mma_tf32(c2[0], aa[s][0], aa[s][1], aa[s][2], aa[s][3],
                     w2f[s][0][0], w2f[s][0][1]);
            mma_tf32(c2[1], aa[s][0], aa[s][1], aa[s][2], aa[s][3],
                     w2f[s][1][0], w2f[s][1][1]);
        }

        // softmax over neighbors (rows) per column
        float mx[2][2], Zs[2][2];
#pragma unroll
        for (int b = 0; b < 2; ++b) {
            mx[b][0] = fmaxf(c2[b][0], c2[b][2]);
            mx[b][1] = fmaxf(c2[b][1], c2[b][3]);
        }
#pragma unroll
        for (int msk = 4; msk <= 16; msk <<= 1)
#pragma unroll
            for (int b = 0; b < 2; ++b)
#pragma unroll
                for (int e = 0; e < 2; ++e)
                    mx[b][e] = fmaxf(mx[b][e],
                                     __shfl_xor_sync(0xffffffffu, mx[b][e], msk));
        float ev[2][4];
#pragma unroll
        for (int b = 0; b < 2; ++b)
#pragma unroll
            for (int q = 0; q < 4; ++q)
                ev[b][q] = exp2f(c2[b][q] - mx[b][q & 1]);
#pragma unroll
        for (int b = 0; b < 2; ++b) {
            Zs[b][0] = ev[b][0] + ev[b][2];
            Zs[b][1] = ev[b][1] + ev[b][3];
        }
#pragma unroll
        for (int msk = 4; msk <= 16; msk <<= 1)
#pragma unroll
            for (int b = 0; b < 2; ++b)
#pragma unroll
                for (int e = 0; e < 2; ++e)
                    Zs[b][e] += __shfl_xor_sync(0xffffffffu, Zs[b][e], msk);

        // store exp weights transposed: wt[o][n]
#pragma unroll
        for (int b = 0; b < 2; ++b)
#pragma unroll
            for (int q = 0; q < 4; ++q)
                wtb[(w * 16 + 2 * tig + (q & 1) + 8 * b) * 20 + gid + 8 * (q >> 1)] = ev[b][q];

        // per-lane 1/Z for column o = lane & 15
        const int zsrc = (lane & 7) >> 1;
        float z00 = __shfl_sync(0xffffffffu, Zs[0][0], zsrc);
        float z01 = __shfl_sync(0xffffffffu, Zs[0][1], zsrc);
        float z10 = __shfl_sync(0xffffffffu, Zs[1][0], zsrc);
        float z11 = __shfl_sync(0xffffffffu, Zs[1][1], zsrc);
        float ze0 = (lane & 1) ? z01 : z00;
        float ze1 = (lane & 1) ? z11 : z10;
        float Zm  = (lane & 8) ? ze1 : ze0;
        float invZ = __frcp_rn(Zm);
        __syncwarp();

        // ---------------- V accumulation ----------------
        ull A20 = 0ull, A21 = 0ull;
#pragma unroll
        for (int h = 0; h < 4; ++h) {
            float4 wq4 = *(const float4*)&wtb[(w * 16 + o) * 20 + 4 * h];
#pragma unroll
            for (int j = 0; j < 4; ++j) {
                int n = 4 * h + j;
                float wn = (j == 0) ? wq4.x : (j == 1) ? wq4.y : (j == 2) ? wq4.z : wq4.w;
                ull wpk = pack2(wn, wn);
                float2 gA = gsm[(w * 16 + n) * 64 + lane];
                float2 gB = gsm[(w * 16 + n) * 64 + 32 + lane];
                A20 = ffma2(wpk, pack2(gA.x, gA.y), A20);
                A21 = ffma2(wpk, pack2(gB.x, gB.y), A21);
            }
        }

        float o0, o1, o2, o3;
        unpack2(A20, o0, o1);
        unpack2(A21, o2, o3);
        out[(size_t)i * CH + lane]      = o0 * invZ;
        out[(size_t)i * CH + lane + 32] = o1 * invZ;
        out[(size_t)i * CH + lane + 64] = o2 * invZ;
        out[(size_t)i * CH + lane + 96] = o3 * invZ;
    }
}

// ---------------------------------------------------------------------------
extern "C" void kernel_launch(void* const* d_in, const int* in_sizes, int n_in,
                              void* d_out, int out_size)
{
    const float* p    = (const float*)d_in[0];
    const float* x    = (const float*)d_in[1];
    const int*   idx  = (const int*)  d_in[2];
    const float* wq   = (const float*)d_in[3];
    const float* bq   = (const float*)d_in[4];
    const float* wk   = (const float*)d_in[5];
    const float* bk   = (const float*)d_in[6];
    const float* wv   = (const float*)d_in[7];
    const float* bv   = (const float*)d_in[8];
    const float* pw1  = (const float*)d_in[9];
    const float* pb1  = (const float*)d_in[10];
    const float* pbng = (const float*)d_in[11];
    const float* pbnb = (const float*)d_in[12];
    const float* pbnm = (const float*)d_in[13];
    const float* pbnv = (const float*)d_in[14];
    const float* pw2  = (const float*)d_in[15];
    const float* pb2  = (const float*)d_in[16];
    const float* bn1g = (const float*)d_in[17];
    const float* bn1b = (const float*)d_in[18];
    const float* bn1m = (const float*)d_in[19];
    const float* bn1v = (const float*)d_in[20];
    const float* ww1  = (const float*)d_in[21];
    const float* wb1  = (const float*)d_in[22];
    const float* bn2g = (const float*)d_in[23];
    const float* bn2b = (const float*)d_in[24];
    const float* bn2m = (const float*)d_in[25];
    const float* bn2v = (const float*)d_in[26];
    const float* ww2  = (const float*)d_in[27];
    const float* wb2  = (const float*)d_in[28];
    float* out = (float*)d_out;

    cudaFuncSetAttribute(attn_kernel,
                         cudaFuncAttributeMaxDynamicSharedMemorySize, SMEM_ATTN);

    prep_kernel<<<NPTS / 256, 256>>>(p);
    qkv_tc_kernel<<<dim3(NPTS / 128, 3), 256>>>(x, wq, bq, wk, bk, wv, bv);
    repack_kernel<<<NPTS * 32 / 256, 256>>>();

    attn_kernel<<<NPTS / (PPW * 4), 128, SMEM_ATTN>>>(
        idx,
        pw1, pb1, pbng, pbnb, pbnm, pbnv, pw2, pb2,
        bn1g, bn1b, bn1m, bn1v, ww1, wb1,
        bn2g, bn2b, bn2m, bn2v, ww2, wb2,
        out);
}

// round 11
// speedup vs baseline: 2.3528x; 1.2172x over previous
#include <cuda_runtime.h>
#include <math.h>

#define NPTS 65536
#define NS   16
#define CH   128
#define EPSB 1e-5f
#define LOG2E 1.4426950408889634f

typedef unsigned long long ull;

__device__ __forceinline__ void cpasync16(unsigned dst, const void* src) {
    asm volatile("cp.async.ca.shared.global [%0],[%1],16;" :: "r"(dst), "l"(src));
}
__device__ __forceinline__ void cpasync8(unsigned dst, const void* src) {
    asm volatile("cp.async.ca.shared.global [%0],[%1],8;" :: "r"(dst), "l"(src));
}
__device__ __forceinline__ void cpcommit() {
    asm volatile("cp.async.commit_group;");
}
template<int N> __device__ __forceinline__ void cpwaitg() {
    asm volatile("cp.async.wait_group %0;" :: "n"(N));
}
__device__ __forceinline__ unsigned f2tf32(float f) {
    unsigned u; asm("cvt.rna.tf32.f32 %0,%1;" : "=r"(u) : "f"(f)); return u;
}
__device__ __forceinline__ unsigned bf16x2hl(float hi, float lo) {
    unsigned d; asm("cvt.rn.bf16x2.f32 %0,%1,%2;" : "=r"(d) : "f"(hi), "f"(lo)); return d;
}
__device__ __forceinline__ float bflo(unsigned u) {
    return __uint_as_float(u << 16);
}
__device__ __forceinline__ float bfhi(unsigned u) {
    return __uint_as_float(u & 0xffff0000u);
}
__device__ __forceinline__ void mma_tf32(float c[4],
                                         unsigned a0, unsigned a1,
                                         unsigned a2, unsigned a3,
                                         unsigned b0, unsigned b1) {
    asm("mma.sync.aligned.m16n8k8.row.col.f32.tf32.tf32.f32 "
        "{%0,%1,%2,%3},{%4,%5,%6,%7},{%8,%9},{%0,%1,%2,%3};"
        : "+f"(c[0]), "+f"(c[1]), "+f"(c[2]), "+f"(c[3])
        : "r"(a0), "r"(a1), "r"(a2), "r"(a3), "r"(b0), "r"(b1));
}
__device__ __forceinline__ void mma_bf16(float c[4],
                                         unsigned a0, unsigned a1,
                                         unsigned a2, unsigned a3,
                                         unsigned b0, unsigned b1) {
    asm("mma.sync.aligned.m16n8k16.row.col.f32.bf16.bf16.f32 "
        "{%0,%1,%2,%3},{%4,%5,%6,%7},{%8,%9},{%0,%1,%2,%3};"
        : "+f"(c[0]), "+f"(c[1]), "+f"(c[2]), "+f"(c[3])
        : "r"(a0), "r"(a1), "r"(a2), "r"(a3), "r"(b0), "r"(b1));
}

// static device scratch (allocation-guard safe)
__device__ float  g_q [(size_t)NPTS * CH];
__device__ ull    g_kb[(size_t)NPTS * 32];   // bf16 K packed: 256B/point
__device__ float4 g_v4[(size_t)NPTS * 32];   // fp32 V interleaved: 512B/point
__device__ float4 g_p4[NPTS];

// ---------------------------------------------------------------------------
__global__ void prep_kernel(const float* __restrict__ p)
{
    int i = blockIdx.x * 256 + threadIdx.x;
    g_p4[i] = make_float4(p[3 * i + 0], p[3 * i + 1], p[3 * i + 2], 0.f);
}

// ---------------------------------------------------------------------------
// Kernel 1: QKV GEMM on tensor cores. Q -> g_q (fp32), K -> g_kb (bf16 packed),
// V -> g_v4 (fp32 float4-interleaved). Mainloop identical to R7-R9 proven.
// ---------------------------------------------------------------------------
__global__ void __launch_bounds__(256)
qkv_tc_kernel(const float* __restrict__ x,
              const float* __restrict__ wq, const float* __restrict__ bq,
              const float* __restrict__ wk, const float* __restrict__ bk,
              const float* __restrict__ wv, const float* __restrict__ bv)
{
    __shared__ unsigned Xs[128][36];
    __shared__ unsigned Ws[128][36];

    const float* W;
    const float* bias;
    const int sel = blockIdx.y;
    if (sel == 0)      { W = wq; bias = bq; }
    else if (sel == 1) { W = wk; bias = bk; }
    else               { W = wv; bias = bv; }

    const int tid  = threadIdx.x;
    const int warp = tid >> 5;
    const int lane = tid & 31;
    const int gid  = lane >> 2;
    const int tig  = lane & 3;
    const int m0   = blockIdx.x * 128;
    const int r0   = warp * 16;

    const int srow = tid >> 1;
    const int skq  = (tid & 1) * 16;

    float c[16][4];
#pragma unroll
    for (int nb = 0; nb < 16; ++nb)
#pragma unroll
        for (int j = 0; j < 4; ++j) c[nb][j] = 0.f;

#pragma unroll 1
    for (int ch = 0; ch < 4; ++ch) {
#pragma unroll
        for (int i = 0; i < 4; ++i) {
            float4 xv = *(const float4*)&x[(size_t)(m0 + srow) * 128 + ch * 32 + skq + 4 * i];
            float4 wv = *(const float4*)&W[(size_t)srow * 128 + ch * 32 + skq + 4 * i];
            uint4 xt, wt;
            xt.x = f2tf32(xv.x); xt.y = f2tf32(xv.y); xt.z = f2tf32(xv.z); xt.w = f2tf32(xv.w);
            wt.x = f2tf32(wv.x); wt.y = f2tf32(wv.y); wt.z = f2tf32(wv.z); wt.w = f2tf32(wv.w);
            *(uint4*)&Xs[srow][skq + 4 * i] = xt;
            *(uint4*)&Ws[srow][skq + 4 * i] = wt;
        }
        __syncthreads();

#pragma unroll
        for (int ks = 0; ks < 4; ++ks) {
            const int k = ks * 8;
            unsigned a0 = Xs[r0 + gid][k + tig];
            unsigned a1 = Xs[r0 + gid + 8][k + tig];
            unsigned a2 = Xs[r0 + gid][k + tig + 4];
            unsigned a3 = Xs[r0 + gid + 8][k + tig + 4];
#pragma unroll
            for (int nb = 0; nb < 16; ++nb) {
                unsigned b0 = Ws[nb * 8 + gid][k + tig];
                unsigned b1 = Ws[nb * 8 + gid][k + tig + 4];
                mma_tf32(c[nb], a0, a1, a2, a3, b0, b1);
            }
        }
        __syncthreads();
    }

    if (sel == 0) {
        // Q: fp32 row-major (as R7-R9)
#pragma unroll
        for (int nb = 0; nb < 16; ++nb) {
            const int col = nb * 8 + 2 * tig;
            const float2 bv = *(const float2*)&bias[col];
            const size_t row = (size_t)(m0 + r0 + gid);
            *(float2*)&g_q[row * 128 + col] =
                make_float2(c[nb][0] + bv.x, c[nb][1] + bv.y);
            *(float2*)&g_q[(row + 8) * 128 + col] =
                make_float2(c[nb][2] + bv.x, c[nb][3] + bv.y);
        }
    } else if (sel == 1) {
        // K: bf16 packed per lane-slot l: {(k(l),k(l+32)),(k(l+64),k(l+96))}
#pragma unroll
        for (int nb = 0; nb < 4; ++nb)
#pragma unroll
            for (int e = 0; e < 2; ++e) {
                const int l = nb * 8 + 2 * tig + e;
                const float b0 = bias[l], b1 = bias[l + 32];
                const float b2 = bias[l + 64], b3 = bias[l + 96];
                unsigned lo = bf16x2hl(c[nb + 4][e] + b1, c[nb][e] + b0);
                unsigned hi = bf16x2hl(c[nb + 12][e] + b3, c[nb + 8][e] + b2);
                g_kb[(size_t)(m0 + r0 + gid) * 32 + l] = ((ull)hi << 32) | lo;
                unsigned lo2 = bf16x2hl(c[nb + 4][e + 2] + b1, c[nb][e + 2] + b0);
                unsigned hi2 = bf16x2hl(c[nb + 12][e + 2] + b3, c[nb + 8][e + 2] + b2);
                g_kb[(size_t)(m0 + r0 + gid + 8) * 32 + l] = ((ull)hi2 << 32) | lo2;
            }
    } else {
        // V: fp32 float4 {v(l),v(l+32),v(l+64),v(l+96)}
#pragma unroll
        for (int nb = 0; nb < 4; ++nb)
#pragma unroll
            for (int e = 0; e < 2; ++e) {
                const int l = nb * 8 + 2 * tig + e;
                const float b0 = bias[l], b1 = bias[l + 32];
                const float b2 = bias[l + 64], b3 = bias[l + 96];
                g_v4[(size_t)(m0 + r0 + gid) * 32 + l] =
                    make_float4(c[nb][e] + b0, c[nb + 4][e] + b1,
                                c[nb + 8][e] + b2, c[nb + 12][e] + b3);
                g_v4[(size_t)(m0 + r0 + gid + 8) * 32 + l] =
                    make_float4(c[nb][e + 2] + b0, c[nb + 4][e + 2] + b1,
                                c[nb + 8][e + 2] + b2, c[nb + 12][e + 2] + b3);
            }
    }
}

// ---------------------------------------------------------------------------
// Kernel 2: tensor-core attention.
// Phase 1: 16-stage K(bf16)+V(fp32) ring filled up-front; consume K only:
//          wp -> wsm (bf16), tt -> ttb (lane 0).
// Phase 2: mma.bf16 logits, BN2+ReLU, mma.tf32 GEMV2, fragment softmax,
//          wtb transpose; V read straight from ring; pe folded algebraically:
//          out = (Σw·v + P2·(Σw·tt) + pb2·Σw) / Z.
// ---------------------------------------------------------------------------
#define PPW 8
// smem offsets (bytes)
#define OFF_KR  0        // ull    [16][4][32] = 16384
#define OFF_VR  16384    // float4 [16][4][32] = 32768
#define OFF_WSM 49152    // unsigned [4][16][68] = 17408
#define OFF_TT  66560    // float4 [4][16] = 1024
#define OFF_WT  67584    // float [4][16][20] = 5120
#define SMEM_ATTN 72704

__global__ void __launch_bounds__(128, 3)
attn_kernel(const int* __restrict__ idx,
            const float* __restrict__ pw1, const float* __restrict__ pb1,
            const float* __restrict__ pbng, const float* __restrict__ pbnb,
            const float* __restrict__ pbnm, const float* __restrict__ pbnv,
            const float* __restrict__ pw2, const float* __restrict__ pb2,
            const float* __restrict__ bn1g, const float* __restrict__ bn1b,
            const float* __restrict__ bn1m, const float* __restrict__ bn1v,
            const float* __restrict__ ww1, const float* __restrict__ wb1,
            const float* __restrict__ bn2g, const float* __restrict__ bn2b,
            const float* __restrict__ bn2m, const float* __restrict__ bn2v,
            const float* __restrict__ ww2, const float* __restrict__ wb2,
            float* __restrict__ out)
{
    extern __shared__ char dsm[];
    ull*      krp = (ull*)(dsm + OFF_KR);
    float4*   vrp = (float4*)(dsm + OFF_VR);
    unsigned* wsm = (unsigned*)(dsm + OFF_WSM);
    float4*   ttb = (float4*)(dsm + OFF_TT);
    float*    wtb = (float*)(dsm + OFF_WT);

    const int lane = threadIdx.x & 31;
    const int w    = (threadIdx.x >> 5) & 3;
    const int gw   = blockIdx.x * (blockDim.x >> 5) + (threadIdx.x >> 5);
    const int gid  = lane >> 2;
    const int tig  = lane & 3;
    const int o    = lane & 15;

    // W1 bf16 B-fragments (R9-proven mapping)
    unsigned bw1[8][2][2];
#pragma unroll
    for (int s = 0; s < 8; ++s)
#pragma unroll
        for (int b = 0; b < 2; ++b)
#pragma unroll
            for (int j = 0; j < 2; ++j) {
                int p = 8 * s + tig + 4 * j;
                int c = (p < 32) ? p : p + 32;
                int oo = 8 * b + gid;
                bw1[s][b][j] = bf16x2hl(ww1[oo * CH + c + 32], ww1[oo * CH + c]);
            }

    // W2 tf32 B-fragments (LOG2E folded)
    unsigned w2f[2][2][2];
#pragma unroll
    for (int s = 0; s < 2; ++s)
#pragma unroll
        for (int b = 0; b < 2; ++b)
#pragma unroll
            for (int j = 0; j < 2; ++j) {
                int u = 8 * s + tig + 4 * j;
                int oo = 8 * b + gid;
                w2f[s][b][j] = f2tf32(ww2[oo * 16 + u] * LOG2E);
            }

    // BN2 constants on c-frag cols
    float s2c[4], b2c[4];
#pragma unroll
    for (int j = 0; j < 4; ++j) {
        int u = 2 * tig + (j & 1) + 8 * (j >> 1);
        float s = bn2g[u] * rsqrtf(bn2v[u] + EPSB);
        s2c[j] = s;
        b2c[j] = bn2b[u] - bn2m[u] * s + wb1[u] * s;
    }

    float s1[4], b1f[4], pw2v[4][3], pb2v[4];
#pragma unroll
    for (int r = 0; r < 4; ++r) {
        int c = lane + 32 * r;
        float s = bn1g[c] * rsqrtf(bn1v[c] + EPSB);
        s1[r]  = s;
        b1f[r] = bn1b[c] - bn1m[c] * s;
        pw2v[r][0] = pw2[c * 3 + 0];
        pw2v[r][1] = pw2[c * 3 + 1];
        pw2v[r][2] = pw2[c * 3 + 2];
        pb2v[r] = pb2[c];
    }
    float Af[9], df[3];
#pragma unroll
    for (int a = 0; a < 3; ++a) {
        float s  = pbng[a] * rsqrtf(pbnv[a] + EPSB);
        float sh = pbnb[a] - pbnm[a] * s;
#pragma unroll
        for (int b = 0; b < 3; ++b) Af[a * 3 + b] = s * pw1[a * 3 + b];
        df[a] = s * pb1[a] + sh;
    }

    const unsigned kr0 =
        (unsigned)__cvta_generic_to_shared(&krp[w * 32 + lane]);
    const unsigned vr0 =
        (unsigned)__cvta_generic_to_shared(&vrp[w * 32 + lane]);

#pragma unroll 1
    for (int t = 0; t < PPW; ++t) {
        const int i = gw * PPW + t;

        const float4 pi = g_p4[i];
        float xqf[4];
#pragma unroll
        for (int r = 0; r < 4; ++r) {
            float xq = g_q[(size_t)i * CH + lane + 32 * r];
            xqf[r] = b1f[r] - s1[r] * xq;
        }
        const int myj = idx[i * NS + o];
        const float4 pjall = g_p4[myj];

        // issue all 16 neighbors' K+V loads (8 commit groups of 2 neighbors)
#pragma unroll
        for (int g = 0; g < 8; ++g) {
#pragma unroll
            for (int e = 0; e < 2; ++e) {
                int n = 2 * g + e;
                int js = __shfl_sync(0xffffffffu, myj, n);
                cpasync8(kr0 + (unsigned)n * 1024u, &g_kb[(size_t)js * 32 + lane]);
                cpasync16(vr0 + (unsigned)n * 2048u, &g_v4[(size_t)js * 32 + lane]);
            }
            cpcommit();
        }

        // ---------------- Phase 1: consume K, build wsm + ttb ----------------
        auto body = [&](int n) {
            ull kk = krp[(n * 4 + w) * 32 + lane];
            unsigned klo = (unsigned)kk, khi = (unsigned)(kk >> 32);
            float gk[4] = {bflo(klo), bfhi(klo), bflo(khi), bfhi(khi)};
            float pr0 = __shfl_sync(0xffffffffu, pjall.x, n) - pi.x;
            float pr1 = __shfl_sync(0xffffffffu, pjall.y, n) - pi.y;
            float pr2 = __shfl_sync(0xffffffffu, pjall.z, n) - pi.z;

            float tt[3];
#pragma unroll
            for (int a = 0; a < 3; ++a) {
                float v = fmaf(pr2, Af[a * 3 + 2],
                          fmaf(pr1, Af[a * 3 + 1],
                          fmaf(pr0, Af[a * 3 + 0], df[a])));
                tt[a] = fmaxf(v, 0.f);
            }
            if (lane == 0)
                ttb[w * 16 + n] = make_float4(tt[0], tt[1], tt[2], 0.f);

            float wp[4];
#pragma unroll
            for (int r = 0; r < 4; ++r) {
                float pe = fmaf(tt[2], pw2v[r][2],
                           fmaf(tt[1], pw2v[r][1],
                           fmaf(tt[0], pw2v[r][0], pb2v[r])));
                wp[r] = fmaxf(fmaf(gk[r] + pe, s1[r], xqf[r]), 0.f);
            }
            wsm[(w * 16 + n) * 68 + lane]      = bf16x2hl(wp[1], wp[0]);
            wsm[(w * 16 + n) * 68 + 32 + lane] = bf16x2hl(wp[3], wp[2]);
        };
        cpwaitg<7>(); body(0);  body(1);
        cpwaitg<6>(); body(2);  body(3);
        cpwaitg<5>(); body(4);  body(5);
        cpwaitg<4>(); body(6);  body(7);
        cpwaitg<3>(); body(8);  body(9);
        cpwaitg<2>(); body(10); body(11);
        cpwaitg<1>(); body(12); body(13);
        cpwaitg<0>(); body(14); body(15);
        __syncwarp();

        // ---------------- Phase 2: tensor-core logits ----------------
        float c1[2][4] = {{0.f, 0.f, 0.f, 0.f}, {0.f, 0.f, 0.f, 0.f}};
#pragma unroll
        for (int s = 0; s < 8; ++s) {
            unsigned a0 = wsm[(w * 16 + gid)     * 68 + 8 * s + tig];
            unsigned a1 = wsm[(w * 16 + gid + 8) * 68 + 8 * s + tig];
            unsigned a2 = wsm[(w * 16 + gid)     * 68 + 8 * s + tig + 4];
            unsigned a3 = wsm[(w * 16 + gid + 8) * 68 + 8 * s + tig + 4];
            mma_bf16(c1[0], a0, a1, a2, a3, bw1[s][0][0], bw1[s][0][1]);
            mma_bf16(c1[1], a0, a1, a2, a3, bw1[s][1][0], bw1[s][1][1]);
        }

        // BN2 + ReLU
        float t1[2][4];
#pragma unroll
        for (int b = 0; b < 2; ++b)
#pragma unroll
            for (int q = 0; q < 4; ++q)
                t1[b][q] = fmaxf(fmaf(c1[b][q], s2c[(q & 1) + 2 * b],
                                      b2c[(q & 1) + 2 * b]), 0.f);

        // permute c-frag -> A-frag for GEMV2
        const int srcA = 4 * gid + (tig >> 1);
        const bool oddt = (tig & 1);
        unsigned aa[2][4];
#pragma unroll
        for (int s = 0; s < 2; ++s) {
            float v0 = __shfl_sync(0xffffffffu, t1[s][0], srcA);
            float v1 = __shfl_sync(0xffffffffu, t1[s][1], srcA);
            float v2 = __shfl_sync(0xffffffffu, t1[s][2], srcA);
            float v3 = __shfl_sync(0xffffffffu, t1[s][3], srcA);
            float u0v = oddt ? v1 : v0;
            float u1v = oddt ? v3 : v2;
            float q0 = __shfl_sync(0xffffffffu, t1[s][0], srcA + 2);
            float q1 = __shfl_sync(0xffffffffu, t1[s][1], srcA + 2);
            float q2 = __shfl_sync(0xffffffffu, t1[s][2], srcA + 2);
            float q3 = __shfl_sync(0xffffffffu, t1[s][3], srcA + 2);
            float u2v = oddt ? q1 : q0;
            float u3v = oddt ? q3 : q2;
            aa[s][0] = f2tf32(u0v); aa[s][1] = f2tf32(u1v);
            aa[s][2] = f2tf32(u2v); aa[s][3] = f2tf32(u3v);
        }

        float c2[2][4] = {{0.f, 0.f, 0.f, 0.f}, {0.f, 0.f, 0.f, 0.f}};
#pragma unroll
        for (int s = 0; s < 2; ++s) {
            mma_tf32(c2[0], aa[s][0], aa[s][1], aa[s][2], aa[s][3],
                     w2f[s][0][0], w2f[s][0][1]);
            mma_tf32(c2[1], aa[s][0], aa[s][1], aa[s][2], aa[s][3],
                     w2f[s][1][0], w2f[s][1][1]);
        }

        // softmax over neighbors (fragment rows)
        float mx[2][2], Zs[2][2];
#pragma unroll
        for (int b = 0; b < 2; ++b) {
            mx[b][0] = fmaxf(c2[b][0], c2[b][2]);
            mx[b][1] = fmaxf(c2[b][1], c2[b][3]);
        }
#pragma unroll
        for (int msk = 4; msk <= 16; msk <<= 1)
#pragma unroll
            for (int b = 0; b < 2; ++b)
#pragma unroll
                for (int e = 0; e < 2; ++e)
                    mx[b][e] = fmaxf(mx[b][e],
                                     __shfl_xor_sync(0xffffffffu, mx[b][e], msk));
        float ev[2][4];
#pragma unroll
        for (int b = 0; b < 2; ++b)
#pragma unroll
            for (int q = 0; q < 4; ++q)
                ev[b][q] = exp2f(c2[b][q] - mx[b][q & 1]);
#pragma unroll
        for (int b = 0; b < 2; ++b) {
            Zs[b][0] = ev[b][0] + ev[b][2];
            Zs[b][1] = ev[b][1] + ev[b][3];
        }
#pragma unroll
        for (int msk = 4; msk <= 16; msk <<= 1)
#pragma unroll
            for (int b = 0; b < 2; ++b)
#pragma unroll
                for (int e = 0; e < 2; ++e)
                    Zs[b][e] += __shfl_xor_sync(0xffffffffu, Zs[b][e], msk);

        // exp weights transposed to wtb[o][n]
#pragma unroll
        for (int b = 0; b < 2; ++b)
#pragma unroll
            for (int q = 0; q < 4; ++q)
                wtb[(w * 16 + 2 * tig + (q & 1) + 8 * b) * 20 + gid + 8 * (q >> 1)] = ev[b][q];

        // unnormalized Z for this lane's column
        const int zsrc = (lane & 7) >> 1;
        float z00 = __shfl_sync(0xffffffffu, Zs[0][0], zsrc);
        float z01 = __shfl_sync(0xffffffffu, Zs[0][1], zsrc);
        float z10 = __shfl_sync(0xffffffffu, Zs[1][0], zsrc);
        float z11 = __shfl_sync(0xffffffffu, Zs[1][1], zsrc);
        float ze0 = (lane & 1) ? z01 : z00;
        float ze1 = (lane & 1) ? z11 : z10;
        float Zm  = (lane & 8) ? ze1 : ze0;
        float invZ = __frcp_rn(Zm);
        __syncwarp();

        // ------------- V accumulation straight from ring + tt fold -------------
        float Acc[4] = {0.f, 0.f, 0.f, 0.f};
        float st0 = 0.f, st1 = 0.f, st2 = 0.f;
#pragma unroll
        for (int h = 0; h < 4; ++h) {
            float4 wq4 = *(const float4*)&wtb[(w * 16 + o) * 20 + 4 * h];
#pragma unroll
            for (int j = 0; j < 4; ++j) {
                int n = 4 * h + j;
                float wn = (j == 0) ? wq4.x : (j == 1) ? wq4.y : (j == 2) ? wq4.z : wq4.w;
                float4 vv = vrp[(n * 4 + w) * 32 + lane];
                float4 t4 = ttb[w * 16 + n];
                Acc[0] = fmaf(wn, vv.x, Acc[0]);
                Acc[1] = fmaf(wn, vv.y, Acc[1]);
                Acc[2] = fmaf(wn, vv.z, Acc[2]);
                Acc[3] = fmaf(wn, vv.w, Acc[3]);
                st0 = fmaf(wn, t4.x, st0);
                st1 = fmaf(wn, t4.y, st1);
                st2 = fmaf(wn, t4.z, st2);
            }
        }

#pragma unroll
        for (int r = 0; r < 4; ++r) {
            float pesum = fmaf(pw2v[r][2], st2,
                          fmaf(pw2v[r][1], st1,
                          fmaf(pw2v[r][0], st0, pb2v[r] * Zm)));
            out[(size_t)i * CH + lane + 32 * r] = (Acc[r] + pesum) * invZ;
        }
    }
}

// ---------------------------------------------------------------------------
extern "C" void kernel_launch(void* const* d_in, const int* in_sizes, int n_in,
                              void* d_out, int out_size)
{
    const float* p    = (const float*)d_in[0];
    const float* x    = (const float*)d_in[1];
    const int*   idx  = (const int*)  d_in[2];
    const float* wq   = (const float*)d_in[3];
    const float* bq   = (const float*)d_in[4];
    const float* wk   = (const float*)d_in[5];
    const float* bk   = (const float*)d_in[6];
    const float* wv   = (const float*)d_in[7];
    const float* bv   = (const float*)d_in[8];
    const float* pw1  = (const float*)d_in[9];
    const float* pb1  = (const float*)d_in[10];
    const float* pbng = (const float*)d_in[11];
    const float* pbnb = (const float*)d_in[12];
    const float* pbnm = (const float*)d_in[13];
    const float* pbnv = (const float*)d_in[14];
    const float* pw2  = (const float*)d_in[15];
    const float* pb2  = (const float*)d_in[16];
    const float* bn1g = (const float*)d_in[17];
    const float* bn1b = (const float*)d_in[18];
    const float* bn1m = (const float*)d_in[19];
    const float* bn1v = (const float*)d_in[20];
    const float* ww1  = (const float*)d_in[21];
    const float* wb1  = (const float*)d_in[22];
    const float* bn2g = (const float*)d_in[23];
    const float* bn2b = (const float*)d_in[24];
    const float* bn2m = (const float*)d_in[25];
    const float* bn2v = (const float*)d_in[26];
    const float* ww2  = (const float*)d_in[27];
    const float* wb2  = (const float*)d_in[28];
    float* out = (float*)d_out;

    cudaFuncSetAttribute(attn_kernel,
                         cudaFuncAttributeMaxDynamicSharedMemorySize, SMEM_ATTN);

    prep_kernel<<<NPTS / 256, 256>>>(p);
    qkv_tc_kernel<<<dim3(NPTS / 128, 3), 256>>>(x, wq, bq, wk, bk, wv, bv);

    attn_kernel<<<NPTS / (PPW * 4), 128, SMEM_ATTN>>>(
        idx,
        pw1, pb1, pbng, pbnb, pbnm, pbnv, pw2, pb2,
        bn1g, bn1b, bn1m, bn1v, ww1, wb1,
        bn2g, bn2b, bn2m, bn2v, ww2, wb2,
        out);
}

// round 12
// speedup vs baseline: 2.6030x; 1.1063x over previous
#include <cuda_runtime.h>
#include <cuda_fp16.h>
#include <math.h>

#define NPTS 65536
#define NS   16
#define CH   128
#define EPSB 1e-5f
#define LOG2E 1.4426950408889634f

typedef unsigned long long ull;

__device__ __forceinline__ void cpasync16(unsigned dst, const void* src) {
    asm volatile("cp.async.ca.shared.global [%0],[%1],16;" :: "r"(dst), "l"(src));
}
__device__ __forceinline__ void cpasync8(unsigned dst, const void* src) {
    asm volatile("cp.async.ca.shared.global [%0],[%1],8;" :: "r"(dst), "l"(src));
}
__device__ __forceinline__ void cpcommit() {
    asm volatile("cp.async.commit_group;");
}
template<int N> __device__ __forceinline__ void cpwaitg() {
    asm volatile("cp.async.wait_group %0;" :: "n"(N));
}
__device__ __forceinline__ unsigned f2tf32(float f) {
    unsigned u; asm("cvt.rna.tf32.f32 %0,%1;" : "=r"(u) : "f"(f)); return u;
}
__device__ __forceinline__ unsigned bf16x2hl(float hi, float lo) {
    unsigned d; asm("cvt.rn.bf16x2.f32 %0,%1,%2;" : "=r"(d) : "f"(hi), "f"(lo)); return d;
}
__device__ __forceinline__ unsigned f16x2hl(float hi, float lo) {
    unsigned d; asm("cvt.rn.f16x2.f32 %0,%1,%2;" : "=r"(d) : "f"(hi), "f"(lo)); return d;
}
__device__ __forceinline__ float bflo(unsigned u) {
    return __uint_as_float(u << 16);
}
__device__ __forceinline__ float bfhi(unsigned u) {
    return __uint_as_float(u & 0xffff0000u);
}
__device__ __forceinline__ void mma_tf32(float c[4],
                                         unsigned a0, unsigned a1,
                                         unsigned a2, unsigned a3,
                                         unsigned b0, unsigned b1) {
    asm("mma.sync.aligned.m16n8k8.row.col.f32.tf32.tf32.f32 "
        "{%0,%1,%2,%3},{%4,%5,%6,%7},{%8,%9},{%0,%1,%2,%3};"
        : "+f"(c[0]), "+f"(c[1]), "+f"(c[2]), "+f"(c[3])
        : "r"(a0), "r"(a1), "r"(a2), "r"(a3), "r"(b0), "r"(b1));
}
__device__ __forceinline__ void mma_bf16(float c[4],
                                         unsigned a0, unsigned a1,
                                         unsigned a2, unsigned a3,
                                         unsigned b0, unsigned b1) {
    asm("mma.sync.aligned.m16n8k16.row.col.f32.bf16.bf16.f32 "
        "{%0,%1,%2,%3},{%4,%5,%6,%7},{%8,%9},{%0,%1,%2,%3};"
        : "+f"(c[0]), "+f"(c[1]), "+f"(c[2]), "+f"(c[3])
        : "r"(a0), "r"(a1), "r"(a2), "r"(a3), "r"(b0), "r"(b1));
}

// static device scratch (allocation-guard safe)
__device__ float  g_q [(size_t)NPTS * CH];
__device__ ull    g_kb[(size_t)NPTS * 32];   // bf16 K packed: 256B/point
__device__ ull    g_vh[(size_t)NPTS * 32];   // fp16 V packed: 256B/point
__device__ float4 g_p4[NPTS];

// ---------------------------------------------------------------------------
__global__ void prep_kernel(const float* __restrict__ p)
{
    int i = blockIdx.x * 256 + threadIdx.x;
    g_p4[i] = make_float4(p[3 * i + 0], p[3 * i + 1], p[3 * i + 2], 0.f);
}

// ---------------------------------------------------------------------------
// Kernel 1: QKV GEMM on tensor cores. Q -> g_q (fp32), K -> g_kb (bf16),
// V -> g_vh (fp16). Mainloop identical to R7-R11 proven.
// ---------------------------------------------------------------------------
__global__ void __launch_bounds__(256)
qkv_tc_kernel(const float* __restrict__ x,
              const float* __restrict__ wq, const float* __restrict__ bq,
              const float* __restrict__ wk, const float* __restrict__ bk,
              const float* __restrict__ wv, const float* __restrict__ bv)
{
    __shared__ unsigned Xs[128][36];
    __shared__ unsigned Ws[128][36];

    const float* W;
    const float* bias;
    const int sel = blockIdx.y;
    if (sel == 0)      { W = wq; bias = bq; }
    else if (sel == 1) { W = wk; bias = bk; }
    else               { W = wv; bias = bv; }

    const int tid  = threadIdx.x;
    const int warp = tid >> 5;
    const int lane = tid & 31;
    const int gid  = lane >> 2;
    const int tig  = lane & 3;
    const int m0   = blockIdx.x * 128;
    const int r0   = warp * 16;

    const int srow = tid >> 1;
    const int skq  = (tid & 1) * 16;

    float c[16][4];
#pragma unroll
    for (int nb = 0; nb < 16; ++nb)
#pragma unroll
        for (int j = 0; j < 4; ++j) c[nb][j] = 0.f;

#pragma unroll 1
    for (int ch = 0; ch < 4; ++ch) {
#pragma unroll
        for (int i = 0; i < 4; ++i) {
            float4 xv = *(const float4*)&x[(size_t)(m0 + srow) * 128 + ch * 32 + skq + 4 * i];
            float4 wv = *(const float4*)&W[(size_t)srow * 128 + ch * 32 + skq + 4 * i];
            uint4 xt, wt;
            xt.x = f2tf32(xv.x); xt.y = f2tf32(xv.y); xt.z = f2tf32(xv.z); xt.w = f2tf32(xv.w);
            wt.x = f2tf32(wv.x); wt.y = f2tf32(wv.y); wt.z = f2tf32(wv.z); wt.w = f2tf32(wv.w);
            *(uint4*)&Xs[srow][skq + 4 * i] = xt;
            *(uint4*)&Ws[srow][skq + 4 * i] = wt;
        }
        __syncthreads();

#pragma unroll
        for (int ks = 0; ks < 4; ++ks) {
            const int k = ks * 8;
            unsigned a0 = Xs[r0 + gid][k + tig];
            unsigned a1 = Xs[r0 + gid + 8][k + tig];
            unsigned a2 = Xs[r0 + gid][k + tig + 4];
            unsigned a3 = Xs[r0 + gid + 8][k + tig + 4];
#pragma unroll
            for (int nb = 0; nb < 16; ++nb) {
                unsigned b0 = Ws[nb * 8 + gid][k + tig];
                unsigned b1 = Ws[nb * 8 + gid][k + tig + 4];
                mma_tf32(c[nb], a0, a1, a2, a3, b0, b1);
            }
        }
        __syncthreads();
    }

    if (sel == 0) {
#pragma unroll
        for (int nb = 0; nb < 16; ++nb) {
            const int col = nb * 8 + 2 * tig;
            const float2 bv = *(const float2*)&bias[col];
            const size_t row = (size_t)(m0 + r0 + gid);
            *(float2*)&g_q[row * 128 + col] =
                make_float2(c[nb][0] + bv.x, c[nb][1] + bv.y);
            *(float2*)&g_q[(row + 8) * 128 + col] =
                make_float2(c[nb][2] + bv.x, c[nb][3] + bv.y);
        }
    } else if (sel == 1) {
        // K: bf16 packed per lane-slot l: {(k(l),k(l+32)),(k(l+64),k(l+96))}
#pragma unroll
        for (int nb = 0; nb < 4; ++nb)
#pragma unroll
            for (int e = 0; e < 2; ++e) {
                const int l = nb * 8 + 2 * tig + e;
                const float b0 = bias[l], b1 = bias[l + 32];
                const float b2 = bias[l + 64], b3 = bias[l + 96];
                unsigned lo = bf16x2hl(c[nb + 4][e] + b1, c[nb][e] + b0);
                unsigned hi = bf16x2hl(c[nb + 12][e] + b3, c[nb + 8][e] + b2);
                g_kb[(size_t)(m0 + r0 + gid) * 32 + l] = ((ull)hi << 32) | lo;
                unsigned lo2 = bf16x2hl(c[nb + 4][e + 2] + b1, c[nb][e + 2] + b0);
                unsigned hi2 = bf16x2hl(c[nb + 12][e + 2] + b3, c[nb + 8][e + 2] + b2);
                g_kb[(size_t)(m0 + r0 + gid + 8) * 32 + l] = ((ull)hi2 << 32) | lo2;
            }
    } else {
        // V: fp16 packed, same layout as K (single rounding)
#pragma unroll
        for (int nb = 0; nb < 4; ++nb)
#pragma unroll
            for (int e = 0; e < 2; ++e) {
                const int l = nb * 8 + 2 * tig + e;
                const float b0 = bias[l], b1 = bias[l + 32];
                const float b2 = bias[l + 64], b3 = bias[l + 96];
                unsigned lo = f16x2hl(c[nb + 4][e] + b1, c[nb][e] + b0);
                unsigned hi = f16x2hl(c[nb + 12][e] + b3, c[nb + 8][e] + b2);
                g_vh[(size_t)(m0 + r0 + gid) * 32 + l] = ((ull)hi << 32) | lo;
                unsigned lo2 = f16x2hl(c[nb + 4][e + 2] + b1, c[nb][e + 2] + b0);
                unsigned hi2 = f16x2hl(c[nb + 12][e + 2] + b3, c[nb + 8][e + 2] + b2);
                g_vh[(size_t)(m0 + r0 + gid + 8) * 32 + l] = ((ull)hi2 << 32) | lo2;
            }
    }
}

// ---------------------------------------------------------------------------
// Kernel 2: tensor-core attention (R11 structure, fp16 V ring, 4 CTAs/SM).
// ---------------------------------------------------------------------------
#define PPW 8
// smem offsets (bytes)
#define OFF_KR  0        // ull [16][4][32]       = 16384
#define OFF_VR  16384    // ull [16][4][32]       = 16384
#define OFF_WSM 32768    // unsigned [4][16][68]  = 17408
#define OFF_TT  50176    // float4 [4][16]        = 1024
#define OFF_WT  51200    // float [4][16][20]     = 5120
#define SMEM_ATTN 56320

__global__ void __launch_bounds__(128, 4)
attn_kernel(const int* __restrict__ idx,
            const float* __restrict__ pw1, const float* __restrict__ pb1,
            const float* __restrict__ pbng, const float* __restrict__ pbnb,
            const float* __restrict__ pbnm, const float* __restrict__ pbnv,
            const float* __restrict__ pw2, const float* __restrict__ pb2,
            const float* __restrict__ bn1g, const float* __restrict__ bn1b,
            const float* __restrict__ bn1m, const float* __restrict__ bn1v,
            const float* __restrict__ ww1, const float* __restrict__ wb1,
            const float* __restrict__ bn2g, const float* __restrict__ bn2b,
            const float* __restrict__ bn2m, const float* __restrict__ bn2v,
            const float* __restrict__ ww2, const float* __restrict__ wb2,
            float* __restrict__ out)
{
    extern __shared__ char dsm[];
    ull*      krp = (ull*)(dsm + OFF_KR);
    ull*      vrp = (ull*)(dsm + OFF_VR);
    unsigned* wsm = (unsigned*)(dsm + OFF_WSM);
    float4*   ttb = (float4*)(dsm + OFF_TT);
    float*    wtb = (float*)(dsm + OFF_WT);

    const int lane = threadIdx.x & 31;
    const int w    = (threadIdx.x >> 5) & 3;
    const int gw   = blockIdx.x * (blockDim.x >> 5) + (threadIdx.x >> 5);
    const int gid  = lane >> 2;
    const int tig  = lane & 3;
    const int o    = lane & 15;

    // W1 bf16 B-fragments (R9-proven mapping)
    unsigned bw1[8][2][2];
#pragma unroll
    for (int s = 0; s < 8; ++s)
#pragma unroll
        for (int b = 0; b < 2; ++b)
#pragma unroll
            for (int j = 0; j < 2; ++j) {
                int p = 8 * s + tig + 4 * j;
                int c = (p < 32) ? p : p + 32;
                int oo = 8 * b + gid;
                bw1[s][b][j] = bf16x2hl(ww1[oo * CH + c + 32], ww1[oo * CH + c]);
            }

    // W2 tf32 B-fragments (LOG2E folded)
    unsigned w2f[2][2][2];
#pragma unroll
    for (int s = 0; s < 2; ++s)
#pragma unroll
        for (int b = 0; b < 2; ++b)
#pragma unroll
            for (int j = 0; j < 2; ++j) {
                int u = 8 * s + tig + 4 * j;
                int oo = 8 * b + gid;
                w2f[s][b][j] = f2tf32(ww2[oo * 16 + u] * LOG2E);
            }

    // BN2 constants on c-frag cols
    float s2c[4], b2c[4];
#pragma unroll
    for (int j = 0; j < 4; ++j) {
        int u = 2 * tig + (j & 1) + 8 * (j >> 1);
        float s = bn2g[u] * rsqrtf(bn2v[u] + EPSB);
        s2c[j] = s;
        b2c[j] = bn2b[u] - bn2m[u] * s + wb1[u] * s;
    }

    float s1[4], b1f[4], pw2v[4][3], pb2v[4];
#pragma unroll
    for (int r = 0; r < 4; ++r) {
        int c = lane + 32 * r;
        float s = bn1g[c] * rsqrtf(bn1v[c] + EPSB);
        s1[r]  = s;
        b1f[r] = bn1b[c] - bn1m[c] * s;
        pw2v[r][0] = pw2[c * 3 + 0];
        pw2v[r][1] = pw2[c * 3 + 1];
        pw2v[r][2] = pw2[c * 3 + 2];
        pb2v[r] = pb2[c];
    }
    float Af[9], df[3];
#pragma unroll
    for (int a = 0; a < 3; ++a) {
        float s  = pbng[a] * rsqrtf(pbnv[a] + EPSB);
        float sh = pbnb[a] - pbnm[a] * s;
#pragma unroll
        for (int b = 0; b < 3; ++b) Af[a * 3 + b] = s * pw1[a * 3 + b];
        df[a] = s * pb1[a] + sh;
    }

    const unsigned kr0 =
        (unsigned)__cvta_generic_to_shared(&krp[w * 32 + lane]);
    const unsigned vr0 =
        (unsigned)__cvta_generic_to_shared(&vrp[w * 32 + lane]);

#pragma unroll 1
    for (int t = 0; t < PPW; ++t) {
        const int i = gw * PPW + t;

        const float4 pi = g_p4[i];
        float xqf[4];
#pragma unroll
        for (int r = 0; r < 4; ++r) {
            float xq = g_q[(size_t)i * CH + lane + 32 * r];
            xqf[r] = b1f[r] - s1[r] * xq;
        }
        const int myj = idx[i * NS + o];
        const float4 pjall = g_p4[myj];

        // issue all 16 neighbors' K+V loads (8 commit groups of 2 neighbors)
#pragma unroll
        for (int g = 0; g < 8; ++g) {
#pragma unroll
            for (int e = 0; e < 2; ++e) {
                int n = 2 * g + e;
                int js = __shfl_sync(0xffffffffu, myj, n);
                cpasync8(kr0 + (unsigned)n * 1024u, &g_kb[(size_t)js * 32 + lane]);
                cpasync8(vr0 + (unsigned)n * 1024u, &g_vh[(size_t)js * 32 + lane]);
            }
            cpcommit();
        }

        // ---------------- Phase 1: consume K, build wsm + ttb ----------------
        auto body = [&](int n) {
            ull kk = krp[(n * 4 + w) * 32 + lane];
            unsigned klo = (unsigned)kk, khi = (unsigned)(kk >> 32);
            float gk[4] = {bflo(klo), bfhi(klo), bflo(khi), bfhi(khi)};
            float pr0 = __shfl_sync(0xffffffffu, pjall.x, n) - pi.x;
            float pr1 = __shfl_sync(0xffffffffu, pjall.y, n) - pi.y;
            float pr2 = __shfl_sync(0xffffffffu, pjall.z, n) - pi.z;

            float tt[3];
#pragma unroll
            for (int a = 0; a < 3; ++a) {
                float v = fmaf(pr2, Af[a * 3 + 2],
                          fmaf(pr1, Af[a * 3 + 1],
                          fmaf(pr0, Af[a * 3 + 0], df[a])));
                tt[a] = fmaxf(v, 0.f);
            }
            if (lane == 0)
                ttb[w * 16 + n] = make_float4(tt[0], tt[1], tt[2], 0.f);

            float wp[4];
#pragma unroll
            for (int r = 0; r < 4; ++r) {
                float pe = fmaf(tt[2], pw2v[r][2],
                           fmaf(tt[1], pw2v[r][1],
                           fmaf(tt[0], pw2v[r][0], pb2v[r])));
                wp[r] = fmaxf(fmaf(gk[r] + pe, s1[r], xqf[r]), 0.f);
            }
            wsm[(w * 16 + n) * 68 + lane]      = bf16x2hl(wp[1], wp[0]);
            wsm[(w * 16 + n) * 68 + 32 + lane] = bf16x2hl(wp[3], wp[2]);
        };
        cpwaitg<7>(); body(0);  body(1);
        cpwaitg<6>(); body(2);  body(3);
        cpwaitg<5>(); body(4);  body(5);
        cpwaitg<4>(); body(6);  body(7);
        cpwaitg<3>(); body(8);  body(9);
        cpwaitg<2>(); body(10); body(11);
        cpwaitg<1>(); body(12); body(13);
        cpwaitg<0>(); body(14); body(15);
        __syncwarp();

        // ---------------- Phase 2: tensor-core logits ----------------
        float c1[2][4] = {{0.f, 0.f, 0.f, 0.f}, {0.f, 0.f, 0.f, 0.f}};
#pragma unroll
        for (int s = 0; s < 8; ++s) {
            unsigned a0 = wsm[(w * 16 + gid)     * 68 + 8 * s + tig];
            unsigned a1 = wsm[(w * 16 + gid + 8) * 68 + 8 * s + tig];
            unsigned a2 = wsm[(w * 16 + gid)     * 68 + 8 * s + tig + 4];
            unsigned a3 = wsm[(w * 16 + gid + 8) * 68 + 8 * s + tig + 4];
            mma_bf16(c1[0], a0, a1, a2, a3, bw1[s][0][0], bw1[s][0][1]);
            mma_bf16(c1[1], a0, a1, a2, a3, bw1[s][1][0], bw1[s][1][1]);
        }

        // BN2 + ReLU
        float t1[2][4];
#pragma unroll
        for (int b = 0; b < 2; ++b)
#pragma unroll
            for (int q = 0; q < 4; ++q)
                t1[b][q] = fmaxf(fmaf(c1[b][q], s2c[(q & 1) + 2 * b],
                                      b2c[(q & 1) + 2 * b]), 0.f);

        // permute c-frag -> A-frag for GEMV2
        const int srcA = 4 * gid + (tig >> 1);
        const bool oddt = (tig & 1);
        unsigned aa[2][4];
#pragma unroll
        for (int s = 0; s < 2; ++s) {
            float v0 = __shfl_sync(0xffffffffu, t1[s][0], srcA);
            float v1 = __shfl_sync(0xffffffffu, t1[s][1], srcA);
            float v2 = __shfl_sync(0xffffffffu, t1[s][2], srcA);
            float v3 = __shfl_sync(0xffffffffu, t1[s][3], srcA);
            float u0v = oddt ? v1 : v0;
            float u1v = oddt ? v3 : v2;
            float q0 = __shfl_sync(0xffffffffu, t1[s][0], srcA + 2);
            float q1 = __shfl_sync(0xffffffffu, t1[s][1], srcA + 2);
            float q2 = __shfl_sync(0xffffffffu, t1[s][2], srcA + 2);
            float q3 = __shfl_sync(0xffffffffu, t1[s][3], srcA + 2);
            float u2v = oddt ? q1 : q0;
            float u3v = oddt ? q3 : q2;
            aa[s][0] = f2tf32(u0v); aa[s][1] = f2tf32(u1v);
            aa[s][2] = f2tf32(u2v); aa[s][3] = f2tf32(u3v);
        }

        float c2[2][4] = {{0.f, 0.f, 0.f, 0.f}, {0.f, 0.f, 0.f, 0.f}};
#pragma unroll
        for (int s = 0; s < 2; ++s) {
            mma_tf32(c2[0], aa[s][0], aa[s][1], aa[s][2], aa[s][3],
                     w2f[s][0][0], w2f[s][0][1]);
            mma_tf32(c2[1], aa[s][0], aa[s][1], aa[s][2], aa[s][3],
                     w2f[s][1][0], w2f[s][1][1]);
        }

        // softmax over neighbors (fragment rows)
        float mx[2][2], Zs[2][2];
#pragma unroll
        for (int b = 0; b < 2; ++b) {
            mx[b][0] = fmaxf(c2[b][0], c2[b][2]);
            mx[b][1] = fmaxf(c2[b][1], c2[b][3]);
        }
#pragma unroll
        for (int msk = 4; msk <= 16; msk <<= 1)
#pragma unroll
            for (int b = 0; b < 2; ++b)
#pragma unroll
                for (int e = 0; e < 2; ++e)
                    mx[b][e] = fmaxf(mx[b][e],
                                     __shfl_xor_sync(0xffffffffu, mx[b][e], msk));
        float ev[2][4];
#pragma unroll
        for (int b = 0; b < 2; ++b)
#pragma unroll
            for (int q = 0; q < 4; ++q)
                ev[b][q] = exp2f(c2[b][q] - mx[b][q & 1]);
#pragma unroll
        for (int b = 0; b < 2; ++b) {
            Zs[b][0] = ev[b][0] + ev[b][2];
            Zs[b][1] = ev[b][1] + ev[b][3];
        }
#pragma unroll
        for (int msk = 4; msk <= 16; msk <<= 1)
#pragma unroll
            for (int b = 0; b < 2; ++b)
#pragma unroll
                for (int e = 0; e < 2; ++e)
                    Zs[b][e] += __shfl_xor_sync(0xffffffffu, Zs[b][e], msk);

        // exp weights transposed to wtb[o][n]
#pragma unroll
        for (int b = 0; b < 2; ++b)
#pragma unroll
            for (int q = 0; q < 4; ++q)
                wtb[(w * 16 + 2 * tig + (q & 1) + 8 * b) * 20 + gid + 8 * (q >> 1)] = ev[b][q];

        // unnormalized Z for this lane's column
        const int zsrc = (lane & 7) >> 1;
        float z00 = __shfl_sync(0xffffffffu, Zs[0][0], zsrc);
        float z01 = __shfl_sync(0xffffffffu, Zs[0][1], zsrc);
        float z10 = __shfl_sync(0xffffffffu, Zs[1][0], zsrc);
        float z11 = __shfl_sync(0xffffffffu, Zs[1][1], zsrc);
        float ze0 = (lane & 1) ? z01 : z00;
        float ze1 = (lane & 1) ? z11 : z10;
        float Zm  = (lane & 8) ? ze1 : ze0;
        float invZ = __frcp_rn(Zm);
        __syncwarp();

        // ------------- V accumulation from fp16 ring + tt fold -------------
        float Acc[4] = {0.f, 0.f, 0.f, 0.f};
        float st0 = 0.f, st1 = 0.f, st2 = 0.f;
#pragma unroll
        for (int h = 0; h < 4; ++h) {
            float4 wq4 = *(const float4*)&wtb[(w * 16 + o) * 20 + 4 * h];
#pragma unroll
            for (int j = 0; j < 4; ++j) {
                int n = 4 * h + j;
                float wn = (j == 0) ? wq4.x : (j == 1) ? wq4.y : (j == 2) ? wq4.z : wq4.w;
                ull vv = vrp[(n * 4 + w) * 32 + lane];
                unsigned vlo = (unsigned)vv, vhi = (unsigned)(vv >> 32);
                float2 f0 = __half22float2(*(const __half2*)&vlo);
                float2 f1 = __half22float2(*(const __half2*)&vhi);
                float4 t4 = ttb[w * 16 + n];
                Acc[0] = fmaf(wn, f0.x, Acc[0]);
                Acc[1] = fmaf(wn, f0.y, Acc[1]);
                Acc[2] = fmaf(wn, f1.x, Acc[2]);
                Acc[3] = fmaf(wn, f1.y, Acc[3]);
                st0 = fmaf(wn, t4.x, st0);
                st1 = fmaf(wn, t4.y, st1);
                st2 = fmaf(wn, t4.z, st2);
            }
        }

#pragma unroll
        for (int r = 0; r < 4; ++r) {
            float pesum = fmaf(pw2v[r][2], st2,
                          fmaf(pw2v[r][1], st1,
                          fmaf(pw2v[r][0], st0, pb2v[r] * Zm)));
            out[(size_t)i * CH + lane + 32 * r] = (Acc[r] + pesum) * invZ;
        }
    }
}

// ---------------------------------------------------------------------------
extern "C" void kernel_launch(void* const* d_in, const int* in_sizes, int n_in,
                              void* d_out, int out_size)
{
    const float* p    = (const float*)d_in[0];
    const float* x    = (const float*)d_in[1];
    const int*   idx  = (const int*)  d_in[2];
    const float* wq   = (const float*)d_in[3];
    const float* bq   = (const float*)d_in[4];
    const float* wk   = (const float*)d_in[5];
    const float* bk   = (const float*)d_in[6];
    const float* wv   = (const float*)d_in[7];
    const float* bv   = (const float*)d_in[8];
    const float* pw1  = (const float*)d_in[9];
    const float* pb1  = (const float*)d_in[10];
    const float* pbng = (const float*)d_in[11];
    const float* pbnb = (const float*)d_in[12];
    const float* pbnm = (const float*)d_in[13];
    const float* pbnv = (const float*)d_in[14];
    const float* pw2  = (const float*)d_in[15];
    const float* pb2  = (const float*)d_in[16];
    const float* bn1g = (const float*)d_in[17];
    const float* bn1b = (const float*)d_in[18];
    const float* bn1m = (const float*)d_in[19];
    const float* bn1v = (const float*)d_in[20];
    const float* ww1  = (const float*)d_in[21];
    const float* wb1  = (const float*)d_in[22];
    const float* bn2g = (const float*)d_in[23];
    const float* bn2b = (const float*)d_in[24];
    const float* bn2m = (const float*)d_in[25];
    const float* bn2v = (const float*)d_in[26];
    const float* ww2  = (const float*)d_in[27];
    const float* wb2  = (const float*)d_in[28];
    float* out = (float*)d_out;

    cudaFuncSetAttribute(attn_kernel,
                         cudaFuncAttributeMaxDynamicSharedMemorySize, SMEM_ATTN);

    prep_kernel<<<NPTS / 256, 256>>>(p);
    qkv_tc_kernel<<<dim3(NPTS / 128, 3), 256>>>(x, wq, bq, wk, bk, wv, bv);

    attn_kernel<<<NPTS / (PPW * 4), 128, SMEM_ATTN>>>(
        idx,
        pw1, pb1, pbng, pbnb, pbnm, pbnv, pw2, pb2,
        bn1g, bn1b, bn1m, bn1v, ww1, wb1,
        bn2g, bn2b, bn2m, bn2v, ww2, wb2,
        out);
}